// round 10
// baseline (speedup 1.0000x reference)
#include <cuda_runtime.h>
#include <cuda_fp16.h>
#include <math.h>
#include <stdint.h>

#define Bn 4
#define Hh 384
#define Ww 1280
#define HW (Hh * Ww)
#define BHW (Bn * HW)

typedef unsigned int u32;

// ---------------- scratch (device globals; half2 packed as u32) --------------
__device__ u32   g_guid[(size_t)Bn * 6 * HW];    // 12 ch as 6 half2 planes
__device__ u32   g_x1  [(size_t)Bn * 16 * HW];   // 32 ch as 16 half2 planes
__device__ u32   g_x2  [(size_t)Bn * 32 * HW];   // 64 ch as 32 half2 planes
__device__ float g_oa  [(size_t)Bn * 24 * HW];   // fp32 planar
// pre-packed fp16 GEMM-B weights: [n][9*CINP] as half2 (u32)
__device__ u32   g_w1[32 * 72];    // NM=32, K9=144
__device__ u32   g_w2[64 * 144];   // NM=64, K9=288
__device__ u32   g_w3[32 * 288];   // NM=32, K9=576

// ---------------- PTX helpers -------------------------------------------------
__device__ __forceinline__ u32 smem_u32(const void* p) {
    u32 a;
    asm("{ .reg .u64 t; cvta.to.shared.u64 t, %1; cvt.u32.u64 %0, t; }" : "=r"(a) : "l"(p));
    return a;
}
__device__ __forceinline__ void ldmA(u32* a, u32 addr) {
    asm volatile("ldmatrix.sync.aligned.m8n8.x4.shared.b16 {%0,%1,%2,%3}, [%4];"
        : "=r"(a[0]), "=r"(a[1]), "=r"(a[2]), "=r"(a[3]) : "r"(addr));
}
__device__ __forceinline__ void ldmB4(u32* b, u32 addr) {
    asm volatile("ldmatrix.sync.aligned.m8n8.x4.shared.b16 {%0,%1,%2,%3}, [%4];"
        : "=r"(b[0]), "=r"(b[1]), "=r"(b[2]), "=r"(b[3]) : "r"(addr));
}
__device__ __forceinline__ void mma16816(float* d, const u32* a, const u32* b) {
    asm volatile("mma.sync.aligned.m16n8k16.row.col.f32.f16.f16.f32 "
        "{%0,%1,%2,%3}, {%4,%5,%6,%7}, {%8,%9}, {%0,%1,%2,%3};"
        : "+f"(d[0]), "+f"(d[1]), "+f"(d[2]), "+f"(d[3])
        : "r"(a[0]), "r"(a[1]), "r"(a[2]), "r"(a[3]), "r"(b[0]), "r"(b[1]));
}

// ---------------- weight prep: OIHW fp32 -> [n][9*CINP] fp16 pairs -----------
__device__ __forceinline__ u32 packw(const float* __restrict__ wg,
                                     int n, int j, int CIN, int CINP, int COUT) {
    int k = 2 * j, t = k / CINP, c = k % CINP;
    float v0 = 0.f, v1 = 0.f;
    if (n < COUT) {
        if (c < CIN)     v0 = __ldg(wg + ((size_t)n * CIN + c) * 9 + t);
        if (c + 1 < CIN) v1 = __ldg(wg + ((size_t)n * CIN + c + 1) * 9 + t);
    }
    __half2 h = __floats2half2_rn(v0, v1);
    return *(u32*)&h;
}
__global__ void prep_w(const float* __restrict__ w1,
                       const float* __restrict__ w2,
                       const float* __restrict__ w3) {
    int i = blockIdx.x * 256 + threadIdx.x;
    const int S1 = 32 * 72, S2 = 64 * 144, S3 = 32 * 288;
    if (i < S1) {
        g_w1[i] = packw(w1, i / 72, i % 72, 12, 16, 32);
    } else if (i < S1 + S2) {
        int q = i - S1;
        g_w2[q] = packw(w2, q / 144, q % 144, 32, 32, 64);
    } else if (i < S1 + S2 + S3) {
        int q = i - S1 - S2;
        g_w3[q] = packw(w3, q / 288, q % 288, 64, 64, 24);
    }
}

// ---------------- kernel 1: disparity warp + guidance (half2 out) ------------
__global__ void warp_guid_k(const float* __restrict__ coarse,
                            const float* __restrict__ normal,
                            const float* __restrict__ left,
                            const float* __restrict__ right,
                            u32* __restrict__ guid) {
    int idx = blockIdx.x * blockDim.x + threadIdx.x;
    if (idx >= BHW) return;
    int x = idx % Ww;
    int y = (idx / Ww) % Hh;
    int b = idx / HW;
    size_t pix = (size_t)y * Ww + x;

    float disp = __ldg(coarse + (size_t)b * HW + pix);
    float xs   = (float)x - disp;
    float x0f  = floorf(xs);
    int   x0   = (int)x0f;
    float w1   = xs - x0f;
    float wgt0 = 1.0f - w1;

    float we[3] = {0.f, 0.f, 0.f};
#pragma unroll
    for (int d = 0; d < 2; ++d) {
        int   xi = x0 + d;
        float vv = (xi >= 0 && xi < Ww) ? 1.0f : 0.0f;
        int   xc = min(max(xi, 0), Ww - 1);
        float w  = (d == 0) ? wgt0 : w1;
#pragma unroll
        for (int c = 0; c < 3; ++c)
            we[c] += w * vv * __ldg(right + ((size_t)(b * 3 + c) * Hh + y) * Ww + xc);
    }

    float v[12];
#pragma unroll
    for (int c = 0; c < 3; ++c) {
        v[c]     = __ldg(normal + (size_t)(b * 3 + c) * HW + pix);
        v[3 + c] = __ldg(left   + (size_t)(b * 3 + c) * HW + pix);
        v[6 + c] = __ldg(right  + (size_t)(b * 3 + c) * HW + pix);
        v[9 + c] = we[c] - v[3 + c];
    }
    u32* gb = guid + (size_t)b * 6 * HW + pix;
#pragma unroll
    for (int p = 0; p < 6; ++p) {
        __half2 h = __floats2half2_rn(v[2 * p], v[2 * p + 1]);
        gb[(size_t)p * HW] = *(u32*)&h;
    }
}

// ---------------- mma.sync implicit-GEMM conv3x3 ------------------------------
// CTA: TILEM pixels of one output row (b,y) x NM out channels.
// NWM x NWN warps; warp tile = (MI*16) M x (NI*8) N -> d[MI][NI][4].
// A staged once as [3 rows][TILEM+2 x][CINP+8 ch] fp16 (no 9x im2col dup);
// tap (ky,kx) A-fragments are ldmatrix at shifted addresses.
// B staged as [NM][9*CINP+8] fp16 from pre-packed global.
template <int CIN, int CINP, int COUT, int NM, int NWM, int NWN,
          int MI, int NI, int TILEM, bool FP16OUT>
__global__ void __launch_bounds__(NWM * NWN * 32)
conv3x3_mma(const u32* __restrict__ in,    // half2 planes [b][CIN/2][H][W]
            const u32* __restrict__ wB,    // packed fp16 pairs [n][K9/2]
            const float* __restrict__ bng, const float* __restrict__ bnb,
            const float* __restrict__ bnm, const float* __restrict__ bnv,
            void* __restrict__ outp) {
    constexpr int NT   = NWM * NWN * 32;
    constexpr int K9   = 9 * CINP;
    constexpr int KP   = K9 + 8;       // B row stride (fp16), conflict-free
    constexpr int ASTR = CINP + 8;     // A x-stride (fp16), conflict-free
    constexpr int PP   = CINP / 2;
    constexpr int AX   = TILEM + 2;

    extern __shared__ char smem[];
    __half* sB = (__half*)smem;                         // NM * KP
    __half* sA = (__half*)(smem + (size_t)NM * KP * 2); // 3*AX*ASTR

    const int tid = threadIdx.x;
    const int x0 = blockIdx.x * TILEM, y = blockIdx.y, b = blockIdx.z;

    // ---- stage B (u32 copy of packed fp16 pairs) ----
    for (int i = tid; i < NM * (K9 / 2); i += NT) {
        int n = i / (K9 / 2), j = i % (K9 / 2);
        *(u32*)(sB + (size_t)n * KP + 2 * j) = __ldg(wB + i);
    }
    // ---- stage A: 3 rows x AX x CINP fp16 (borders / pad channels zeroed) ---
    const u32* inb = in + (size_t)b * (CIN / 2) * HW;
    for (int i = tid; i < 3 * PP * AX; i += NT) {
        int xloc = i % AX;
        int rp   = i / AX;
        int r = rp / PP, p = rp % PP;
        int yy = y + r - 1, xx = x0 - 1 + xloc;
        u32 v = 0;
        if (p < CIN / 2 && yy >= 0 && yy < Hh && (unsigned)xx < (unsigned)Ww)
            v = __ldg(inb + (size_t)p * HW + (size_t)yy * Ww + xx);
        *(u32*)(sA + ((size_t)(r * AX + xloc)) * ASTR + 2 * p) = v;
    }
    __syncthreads();

    const int lane = tid & 31, wid = tid >> 5;
    const int wm = wid % NWM, wn = wid / NWM;
    const int m0 = wm * (MI * 16);

    const u32 aBase = smem_u32(sA);
    const u32 bBase = smem_u32(sB);
    const int rowA = lane & 15;
    const int kofA = (lane >> 4) * 8;
    // ldmB4 lane map: mats 0/1 = n-group nio (k+0, k+8); mats 2/3 = nio+1
    const int nB = wn * (NI * 8) + (lane & 7) + ((lane >> 4) << 3);
    const int kB = ((lane >> 3) & 1) * 8;
    const u32 bAddr0 = bBase + (u32)((nB * KP + kB) * 2);

    float d[MI][NI][4];
#pragma unroll
    for (int mi = 0; mi < MI; ++mi)
#pragma unroll
        for (int ni = 0; ni < NI; ++ni)
#pragma unroll
            for (int c = 0; c < 4; ++c) d[mi][ni][c] = 0.0f;

#pragma unroll
    for (int t = 0; t < 9; ++t) {
        const int ky = t / 3, kx = t % 3;
        const u32 aT = aBase + (u32)(((ky * AX + m0 + rowA + kx) * ASTR + kofA) * 2);
        const u32 bT = bAddr0 + (u32)(t * CINP * 2);
#pragma unroll
        for (int kk = 0; kk < CINP / 16; ++kk) {
            u32 a[MI][4];
#pragma unroll
            for (int mi = 0; mi < MI; ++mi)
                ldmA(a[mi], aT + (u32)(mi * 16 * ASTR * 2) + kk * 32);
#pragma unroll
            for (int nio = 0; nio < NI; nio += 2) {
                u32 bb[4];
                ldmB4(bb, bT + kk * 32 + (u32)(nio * 8 * KP * 2));
#pragma unroll
                for (int mi = 0; mi < MI; ++mi) {
                    mma16816(d[mi][nio],     a[mi], bb);
                    mma16816(d[mi][nio + 1], a[mi], bb + 2);
                }
            }
        }
    }

    // ---- epilogue ----
    const int r4 = lane >> 2, c4 = lane & 3;
#pragma unroll
    for (int ni = 0; ni < NI; ++ni) {
        int ch = wn * (NI * 8) + ni * 8 + c4 * 2;
        if (FP16OUT) {
            float s0 = __ldg(bng + ch)     * rsqrtf(__ldg(bnv + ch) + 1e-5f);
            float t0 = __ldg(bnb + ch)     - __ldg(bnm + ch) * s0;
            float s1 = __ldg(bng + ch + 1) * rsqrtf(__ldg(bnv + ch + 1) + 1e-5f);
            float t1 = __ldg(bnb + ch + 1) - __ldg(bnm + ch + 1) * s1;
#pragma unroll
            for (int mi = 0; mi < MI; ++mi) {
                int x = x0 + m0 + mi * 16 + r4;
                u32* oh = (u32*)outp + (size_t)b * (COUT / 2) * HW
                                     + (size_t)(ch >> 1) * HW + (size_t)y * Ww;
                float v00 = fmaxf(d[mi][ni][0] * s0 + t0, 0.f);
                float v01 = fmaxf(d[mi][ni][1] * s1 + t1, 0.f);
                float v10 = fmaxf(d[mi][ni][2] * s0 + t0, 0.f);
                float v11 = fmaxf(d[mi][ni][3] * s1 + t1, 0.f);
                __half2 h0 = __floats2half2_rn(v00, v01);
                __half2 h1 = __floats2half2_rn(v10, v11);
                oh[x]     = *(u32*)&h0;
                oh[x + 8] = *(u32*)&h1;
            }
        } else if (ch < COUT) {
#pragma unroll
            for (int mi = 0; mi < MI; ++mi) {
                int x = x0 + m0 + mi * 16 + r4;
                float* of = (float*)outp + (size_t)b * COUT * HW + (size_t)y * Ww;
                of[(size_t)ch * HW + x]           = d[mi][ni][0];
                of[(size_t)(ch + 1) * HW + x]     = d[mi][ni][1];
                of[(size_t)ch * HW + x + 8]       = d[mi][ni][2];
                of[(size_t)(ch + 1) * HW + x + 8] = d[mi][ni][3];
            }
        }
    }
}

// ---------------- bilinear with border-validity masking ----------------------
__device__ __forceinline__ float bilin(const float* __restrict__ img, float ys, float xs) {
    float y0f = floorf(ys), x0f = floorf(xs);
    int y0 = (int)y0f, x0 = (int)x0f;
    float wy1 = ys - y0f, wx1 = xs - x0f;
    float wy0 = 1.0f - wy1, wx0 = 1.0f - wx1;
    float out = 0.0f;
#pragma unroll
    for (int dy = 0; dy < 2; ++dy) {
        int yy = y0 + dy;
        float wy = dy ? wy1 : wy0;
        bool vy = (yy >= 0 && yy < Hh);
        int yc = min(max(yy, 0), Hh - 1);
#pragma unroll
        for (int dx = 0; dx < 2; ++dx) {
            int xx = x0 + dx;
            float wx = dx ? wx1 : wx0;
            float vv = (vy && xx >= 0 && xx < Ww) ? 1.0f : 0.0f;
            int xc = min(max(xx, 0), Ww - 1);
            out += wy * wx * vv * __ldg(img + (size_t)yc * Ww + xc);
        }
    }
    return out;
}

// ---------------- kernel 5: affinity normalization + propagation -------------
__global__ void propagate_k(const float* __restrict__ oa,
                            const float* __restrict__ conf,
                            const float* __restrict__ coarse,
                            const float* __restrict__ ascp,
                            float* __restrict__ out) {
    int idx = blockIdx.x * blockDim.x + threadIdx.x;
    if (idx >= BHW) return;
    int x = idx % Ww;
    int y = (idx / Ww) % Hh;
    int b = idx / HW;

    const float asc = __ldg(ascp) + 1e-8f;
    const float* oab   = oa + (size_t)b * 24 * HW + (size_t)y * Ww + x;
    const float* confb = conf + (size_t)b * HW;
    const float* coarb = coarse + (size_t)b * HW;

    float offy[8], offx[8], aff[8];
#pragma unroll
    for (int n = 0; n < 8; ++n) {
        offy[n] = __ldg(oab + (size_t)(2 * n) * HW);
        offx[n] = __ldg(oab + (size_t)(2 * n + 1) * HW);
        float a = tanhf(__ldg(oab + (size_t)(16 + n) * HW)) / asc;
        float ca = bilin(confb, (float)y + offy[n], (float)x + offx[n]);
        aff[n] = a * ca;
    }
    float s = 1e-4f;
#pragma unroll
    for (int n = 0; n < 8; ++n) s += fabsf(aff[n]);
    s = fmaxf(s, 1.0f);
    float suma = 0.0f;
#pragma unroll
    for (int n = 0; n < 8; ++n) { aff[n] /= s; suma += aff[n]; }
    float aref = 1.0f - suma;

    float inter = 0.0f;
#pragma unroll
    for (int k = 0; k < 9; ++k) {
        float ky = (float)(k / 3) - 1.0f;
        float kx = (float)(k % 3) - 1.0f;
        float oy, ox, a;
        if (k < 4)       { oy = offy[k];     ox = offx[k];     a = aff[k];     }
        else if (k == 4) { oy = 0.0f;        ox = 0.0f;        a = aref;       }
        else             { oy = offy[k - 1]; ox = offx[k - 1]; a = aff[k - 1]; }
        float sv = bilin(coarb, (float)y + ky + oy, (float)x + kx + ox);
        inter += a * sv;
    }
    inter = fmaxf(inter, 0.0f);
    float cd = __ldg(coarb + (size_t)y * Ww + x);
    out[idx] = fmaxf(0.7f * cd + 0.3f * inter, 0.0f);
}

// ---------------- launch ------------------------------------------------------
extern "C" void kernel_launch(void* const* d_in, const int* in_sizes, int n_in,
                              void* d_out, int out_size) {
    const float* coarse  = (const float*)d_in[0];
    const float* normal  = (const float*)d_in[1];
    const float* left    = (const float*)d_in[2];
    const float* right   = (const float*)d_in[3];
    const float* conf    = (const float*)d_in[4];
    const float* conv1_w = (const float*)d_in[5];
    const float* bn1_g   = (const float*)d_in[6];
    const float* bn1_b   = (const float*)d_in[7];
    const float* bn1_m   = (const float*)d_in[8];
    const float* bn1_v   = (const float*)d_in[9];
    const float* conv2_w = (const float*)d_in[10];
    const float* bn2_g   = (const float*)d_in[11];
    const float* bn2_b   = (const float*)d_in[12];
    const float* bn2_m   = (const float*)d_in[13];
    const float* bn2_v   = (const float*)d_in[14];
    const float* conv3_w = (const float*)d_in[15];
    const float* asc     = (const float*)d_in[16];
    float* out = (float*)d_out;

    u32 *guid, *x1, *x2, *w1, *w2, *w3;
    float* oa;
    cudaGetSymbolAddress((void**)&guid, g_guid);
    cudaGetSymbolAddress((void**)&x1, g_x1);
    cudaGetSymbolAddress((void**)&x2, g_x2);
    cudaGetSymbolAddress((void**)&oa, g_oa);
    cudaGetSymbolAddress((void**)&w1, g_w1);
    cudaGetSymbolAddress((void**)&w2, g_w2);
    cudaGetSymbolAddress((void**)&w3, g_w3);

    // smem = NM*(K9+8)*2 (B) + 3*258*(CINP+8)*2 (A)
    const int smem1 = 32 * 152 * 2 + 3 * 258 * 24 * 2;   //  46,880
    const int smem2 = 64 * 296 * 2 + 3 * 258 * 40 * 2;   //  99,808
    const int smem3 = 32 * 584 * 2 + 3 * 258 * 72 * 2;   // 148,832
    cudaFuncSetAttribute(
        (const void*)conv3x3_mma<12, 16, 32, 32, 4, 1, 4, 4, 256, true>,
        cudaFuncAttributeMaxDynamicSharedMemorySize, smem1);
    cudaFuncSetAttribute(
        (const void*)conv3x3_mma<32, 32, 64, 64, 4, 2, 4, 4, 256, true>,
        cudaFuncAttributeMaxDynamicSharedMemorySize, smem2);
    cudaFuncSetAttribute(
        (const void*)conv3x3_mma<64, 64, 24, 32, 4, 1, 4, 4, 256, false>,
        cudaFuncAttributeMaxDynamicSharedMemorySize, smem3);

    // 0) weight prep (fp32 OIHW -> packed fp16 GEMM-B)
    prep_w<<<(32 * 72 + 64 * 144 + 32 * 288 + 255) / 256, 256>>>(conv1_w, conv2_w, conv3_w);

    // 1) warp + guidance (half2 out)
    warp_guid_k<<<(BHW + 255) / 256, 256>>>(coarse, normal, left, right, guid);

    dim3 cg(Ww / 256, Hh, Bn);   // (5, 384, 4)

    // 2) conv1 + bn + relu  (12 -> 32): 4 warps, warp tile 64x32
    conv3x3_mma<12, 16, 32, 32, 4, 1, 4, 4, 256, true><<<cg, 128, smem1>>>(
        guid, w1, bn1_g, bn1_b, bn1_m, bn1_v, x1);

    // 3) conv2 + bn + relu  (32 -> 64): 8 warps, warp tile 64x32
    conv3x3_mma<32, 32, 64, 64, 4, 2, 4, 4, 256, true><<<cg, 256, smem2>>>(
        x1, w2, bn2_g, bn2_b, bn2_m, bn2_v, x2);

    // 4) conv3 (64 -> 24, N padded to 32): 4 warps, warp tile 64x32
    conv3x3_mma<64, 64, 24, 32, 4, 1, 4, 4, 256, false><<<cg, 128, smem3>>>(
        x2, w3, nullptr, nullptr, nullptr, nullptr, oa);

    // 5) propagation epilogue
    propagate_k<<<(BHW + 255) / 256, 256>>>(oa, conf, coarse, asc, out);
}

// round 11
// speedup vs baseline: 1.5494x; 1.5494x over previous
#include <cuda_runtime.h>
#include <cuda_fp16.h>
#include <math.h>
#include <stdint.h>

#define Bn 4
#define Hh 384
#define Ww 1280
#define HW (Hh * Ww)
#define BHW (Bn * HW)

typedef unsigned int u32;

// ---------------- scratch (device globals; half2 packed as u32) --------------
__device__ u32 g_guid[(size_t)Bn * 6 * HW];    // 12 ch as 6 half2 planes
__device__ u32 g_x1  [(size_t)Bn * 16 * HW];   // 32 ch as 16 half2 planes
__device__ u32 g_x2  [(size_t)Bn * 32 * HW];   // 64 ch as 32 half2 planes
// pre-packed fp16 GEMM-B weights: [n][9*CINP] as half2 (u32)
__device__ u32 g_w1[32 * 72];    // NM=32, K9=144
__device__ u32 g_w2[64 * 144];   // NM=64, K9=288
__device__ u32 g_w3[32 * 288];   // NM=32, K9=576

// ---------------- PTX helpers -------------------------------------------------
__device__ __forceinline__ u32 smem_u32(const void* p) {
    u32 a;
    asm("{ .reg .u64 t; cvta.to.shared.u64 t, %1; cvt.u32.u64 %0, t; }" : "=r"(a) : "l"(p));
    return a;
}
__device__ __forceinline__ void ldmA(u32* a, u32 addr) {
    asm volatile("ldmatrix.sync.aligned.m8n8.x4.shared.b16 {%0,%1,%2,%3}, [%4];"
        : "=r"(a[0]), "=r"(a[1]), "=r"(a[2]), "=r"(a[3]) : "r"(addr));
}
__device__ __forceinline__ void ldmB(u32* b, u32 addr) {
    asm volatile("ldmatrix.sync.aligned.m8n8.x2.shared.b16 {%0,%1}, [%2];"
        : "=r"(b[0]), "=r"(b[1]) : "r"(addr));
}
__device__ __forceinline__ void mma16816(float* d, const u32* a, const u32* b) {
    asm volatile("mma.sync.aligned.m16n8k16.row.col.f32.f16.f16.f32 "
        "{%0,%1,%2,%3}, {%4,%5,%6,%7}, {%8,%9}, {%0,%1,%2,%3};"
        : "+f"(d[0]), "+f"(d[1]), "+f"(d[2]), "+f"(d[3])
        : "r"(a[0]), "r"(a[1]), "r"(a[2]), "r"(a[3]), "r"(b[0]), "r"(b[1]));
}

// ---------------- weight prep: OIHW fp32 -> [n][9*CINP] fp16 pairs -----------
__device__ __forceinline__ u32 packw(const float* __restrict__ wg,
                                     int n, int j, int CIN, int CINP, int COUT) {
    int k = 2 * j, t = k / CINP, c = k % CINP;
    float v0 = 0.f, v1 = 0.f;
    if (n < COUT) {
        if (c < CIN)     v0 = __ldg(wg + ((size_t)n * CIN + c) * 9 + t);
        if (c + 1 < CIN) v1 = __ldg(wg + ((size_t)n * CIN + c + 1) * 9 + t);
    }
    __half2 h = __floats2half2_rn(v0, v1);
    return *(u32*)&h;
}
__global__ void prep_w(const float* __restrict__ w1,
                       const float* __restrict__ w2,
                       const float* __restrict__ w3) {
    int i = blockIdx.x * 256 + threadIdx.x;
    const int S1 = 32 * 72, S2 = 64 * 144, S3 = 32 * 288;
    if (i < S1) {
        g_w1[i] = packw(w1, i / 72, i % 72, 12, 16, 32);
    } else if (i < S1 + S2) {
        int q = i - S1;
        g_w2[q] = packw(w2, q / 144, q % 144, 32, 32, 64);
    } else if (i < S1 + S2 + S3) {
        int q = i - S1 - S2;
        g_w3[q] = packw(w3, q / 288, q % 288, 64, 64, 24);
    }
}

// ---------------- kernel 1: disparity warp + guidance (half2 out) ------------
__global__ void warp_guid_k(const float* __restrict__ coarse,
                            const float* __restrict__ normal,
                            const float* __restrict__ left,
                            const float* __restrict__ right,
                            u32* __restrict__ guid) {
    int idx = blockIdx.x * blockDim.x + threadIdx.x;
    if (idx >= BHW) return;
    int x = idx % Ww;
    int y = (idx / Ww) % Hh;
    int b = idx / HW;
    size_t pix = (size_t)y * Ww + x;

    float disp = __ldg(coarse + (size_t)b * HW + pix);
    float xs   = (float)x - disp;
    float x0f  = floorf(xs);
    int   x0   = (int)x0f;
    float w1   = xs - x0f;
    float wgt0 = 1.0f - w1;

    float we[3] = {0.f, 0.f, 0.f};
#pragma unroll
    for (int d = 0; d < 2; ++d) {
        int   xi = x0 + d;
        float vv = (xi >= 0 && xi < Ww) ? 1.0f : 0.0f;
        int   xc = min(max(xi, 0), Ww - 1);
        float w  = (d == 0) ? wgt0 : w1;
#pragma unroll
        for (int c = 0; c < 3; ++c)
            we[c] += w * vv * __ldg(right + ((size_t)(b * 3 + c) * Hh + y) * Ww + xc);
    }

    float v[12];
#pragma unroll
    for (int c = 0; c < 3; ++c) {
        v[c]     = __ldg(normal + (size_t)(b * 3 + c) * HW + pix);
        v[3 + c] = __ldg(left   + (size_t)(b * 3 + c) * HW + pix);
        v[6 + c] = __ldg(right  + (size_t)(b * 3 + c) * HW + pix);
        v[9 + c] = we[c] - v[3 + c];
    }
    u32* gb = guid + (size_t)b * 6 * HW + pix;
#pragma unroll
    for (int p = 0; p < 6; ++p) {
        __half2 h = __floats2half2_rn(v[2 * p], v[2 * p + 1]);
        gb[(size_t)p * HW] = *(u32*)&h;
    }
}

// ---------------- bilinear with border-validity masking ----------------------
__device__ __forceinline__ float bilin(const float* __restrict__ img, float ys, float xs) {
    float y0f = floorf(ys), x0f = floorf(xs);
    int y0 = (int)y0f, x0 = (int)x0f;
    float wy1 = ys - y0f, wx1 = xs - x0f;
    float wy0 = 1.0f - wy1, wx0 = 1.0f - wx1;
    float out = 0.0f;
#pragma unroll
    for (int dy = 0; dy < 2; ++dy) {
        int yy = y0 + dy;
        float wy = dy ? wy1 : wy0;
        bool vy = (yy >= 0 && yy < Hh);
        int yc = min(max(yy, 0), Hh - 1);
#pragma unroll
        for (int dx = 0; dx < 2; ++dx) {
            int xx = x0 + dx;
            float wx = dx ? wx1 : wx0;
            float vv = (vy && xx >= 0 && xx < Ww) ? 1.0f : 0.0f;
            int xc = min(max(xx, 0), Ww - 1);
            out += wy * wx * vv * __ldg(img + (size_t)yc * Ww + xc);
        }
    }
    return out;
}

// ---------------- mma.sync implicit-GEMM conv3x3 (R6 shape, optional fusion) --
// CTA: 128 pixels of one output row (b,y) x NM out channels. 256 thr = 8 warps,
// warp grid 4(M) x 2(N): warp tile 32 x WN.
// A staged once as [3 rows][130 x][CINP+8 ch] fp16 (no 9x im2col duplication);
// tap (ky,kx) A-fragments are ldmatrix at shifted addresses.
// B staged as [NM][9*CINP + 8] fp16 from pre-packed global.
// FUSE (conv3): transpose 24-ch outputs through smem, then threads 0-127 run the
// affinity normalization + non-local propagation epilogue and write final out.
template <int CIN, int CINP, int COUT, int NM, int WN, bool FP16OUT, bool FUSE>
__global__ void __launch_bounds__(256)
conv3x3_mma(const u32* __restrict__ in,    // half2 planes [b][CIN/2][H][W]
            const u32* __restrict__ wB,    // packed fp16 pairs [n][K9/2]
            const float* __restrict__ bng, const float* __restrict__ bnb,
            const float* __restrict__ bnm, const float* __restrict__ bnv,
            const float* __restrict__ conf, const float* __restrict__ coarse,
            const float* __restrict__ ascp,
            void* __restrict__ outp) {
    constexpr int K9   = 9 * CINP;
    constexpr int KP   = K9 + 8;       // B row stride (fp16), conflict-free
    constexpr int ASTR = CINP + 8;     // A x-stride (fp16), conflict-free
    constexpr int PP   = CINP / 2;
    constexpr int NI   = WN / 8;

    extern __shared__ char smem[];
    __half* sB = (__half*)smem;                         // NM * KP
    __half* sA = (__half*)(smem + (size_t)NM * KP * 2); // 3*130*ASTR

    const int tid = threadIdx.x;
    const int x0 = blockIdx.x * 128, y = blockIdx.y, b = blockIdx.z;

    // ---- stage B (u32 copy of packed fp16 pairs) ----
    for (int i = tid; i < NM * (K9 / 2); i += 256) {
        int n = i / (K9 / 2), j = i % (K9 / 2);
        *(u32*)(sB + (size_t)n * KP + 2 * j) = __ldg(wB + i);
    }
    // ---- stage A: 3 rows x 130 x CINP fp16 (pad channels / borders zeroed) --
    const u32* inb = in + (size_t)b * (CIN / 2) * HW;
    for (int i = tid; i < 3 * PP * 130; i += 256) {
        int xloc = i % 130;
        int rp   = i / 130;
        int r = rp / PP, p = rp % PP;
        int yy = y + r - 1, xx = x0 - 1 + xloc;
        u32 v = 0;
        if (p < CIN / 2 && yy >= 0 && yy < Hh && (unsigned)xx < (unsigned)Ww)
            v = __ldg(inb + (size_t)p * HW + (size_t)yy * Ww + xx);
        *(u32*)(sA + ((size_t)(r * 130 + xloc)) * ASTR + 2 * p) = v;
    }
    __syncthreads();

    const int lane = tid & 31, wid = tid >> 5;
    const int wm = wid & 3, wn = wid >> 2;
    const int m0 = wm * 32;

    const u32 aBase = smem_u32(sA);
    const u32 bBase = smem_u32(sB);
    const int rowA = lane & 15;
    const int kofA = (lane >> 4) * 8;
    const int rowB = lane & 7;
    const int kofB = ((lane >> 3) & 1) * 8;

    float d[2][NI][4];
#pragma unroll
    for (int mi = 0; mi < 2; ++mi)
#pragma unroll
        for (int ni = 0; ni < NI; ++ni)
#pragma unroll
            for (int c = 0; c < 4; ++c) d[mi][ni][c] = 0.0f;

#pragma unroll
    for (int t = 0; t < 9; ++t) {
        const int ky = t / 3, kx = t % 3;
        u32 aRow0 = aBase + (u32)(((ky * 130 + m0 + rowA + kx) * ASTR + kofA) * 2);
        u32 aRow1 = aRow0 + 16 * ASTR * 2;
        u32 bRow  = bBase + (u32)((((wn * WN + rowB) * KP) + t * CINP + kofB) * 2);
#pragma unroll
        for (int kk = 0; kk < CINP / 16; ++kk) {
            u32 a0[4], a1[4];
            ldmA(a0, aRow0 + kk * 32);
            ldmA(a1, aRow1 + kk * 32);
#pragma unroll
            for (int ni = 0; ni < NI; ++ni) {
                u32 bb[2];
                ldmB(bb, bRow + (u32)(ni * 8 * KP * 2) + kk * 32);
                mma16816(d[0][ni], a0, bb);
                mma16816(d[1][ni], a1, bb);
            }
        }
    }

    const int r4 = lane >> 2, c4 = lane & 3;

    if (!FUSE) {
        // ---- BN + ReLU epilogue, half2 planar out ----
#pragma unroll
        for (int ni = 0; ni < NI; ++ni) {
            int ch = wn * WN + ni * 8 + c4 * 2;
            float s0 = __ldg(bng + ch)     * rsqrtf(__ldg(bnv + ch) + 1e-5f);
            float t0 = __ldg(bnb + ch)     - __ldg(bnm + ch) * s0;
            float s1 = __ldg(bng + ch + 1) * rsqrtf(__ldg(bnv + ch + 1) + 1e-5f);
            float t1 = __ldg(bnb + ch + 1) - __ldg(bnm + ch + 1) * s1;
#pragma unroll
            for (int mi = 0; mi < 2; ++mi) {
                int x = x0 + m0 + mi * 16 + r4;
                u32* oh = (u32*)outp + (size_t)b * (COUT / 2) * HW
                                     + (size_t)(ch >> 1) * HW + (size_t)y * Ww;
                float v00 = fmaxf(d[mi][ni][0] * s0 + t0, 0.f);
                float v01 = fmaxf(d[mi][ni][1] * s1 + t1, 0.f);
                float v10 = fmaxf(d[mi][ni][2] * s0 + t0, 0.f);
                float v11 = fmaxf(d[mi][ni][3] * s1 + t1, 0.f);
                __half2 h0 = __floats2half2_rn(v00, v01);
                __half2 h1 = __floats2half2_rn(v10, v11);
                oh[x]     = *(u32*)&h0;
                oh[x + 8] = *(u32*)&h1;
            }
        }
    } else {
        // ---- fused propagation epilogue (conv3 path, 8 warps) ----
        __syncthreads();                       // mainloop smem reads done
        float* s_t = (float*)smem;             // [128 px][25] transpose buffer
#pragma unroll
        for (int ni = 0; ni < NI; ++ni) {
            int ch = wn * WN + ni * 8 + c4 * 2;
            if (ch < 24) {
#pragma unroll
                for (int mi = 0; mi < 2; ++mi) {
                    int px = m0 + mi * 16 + r4;
                    s_t[px * 25 + ch]           = d[mi][ni][0];
                    s_t[px * 25 + ch + 1]       = d[mi][ni][1];
                    s_t[(px + 8) * 25 + ch]     = d[mi][ni][2];
                    s_t[(px + 8) * 25 + ch + 1] = d[mi][ni][3];
                }
            }
        }
        __syncthreads();

        if (tid < 128) {
            const int px = tid;                // 0..127
            const int x = x0 + px;
            const float asc = __ldg(ascp) + 1e-8f;
            const float* confb = conf + (size_t)b * HW;
            const float* coarb = coarse + (size_t)b * HW;
            const float* row = s_t + px * 25;

            float offy[8], offx[8], aff[8];
#pragma unroll
            for (int n = 0; n < 8; ++n) {
                offy[n] = row[2 * n];
                offx[n] = row[2 * n + 1];
                float a = tanhf(row[16 + n]) / asc;
                float ca = bilin(confb, (float)y + offy[n], (float)x + offx[n]);
                aff[n] = a * ca;
            }
            float s = 1e-4f;
#pragma unroll
            for (int n = 0; n < 8; ++n) s += fabsf(aff[n]);
            s = fmaxf(s, 1.0f);
            float suma = 0.0f;
#pragma unroll
            for (int n = 0; n < 8; ++n) { aff[n] /= s; suma += aff[n]; }
            float aref = 1.0f - suma;

            float inter = 0.0f;
#pragma unroll
            for (int k = 0; k < 9; ++k) {
                float kyf = (float)(k / 3) - 1.0f;
                float kxf = (float)(k % 3) - 1.0f;
                float oy, ox, a;
                if (k < 4)       { oy = offy[k];     ox = offx[k];     a = aff[k];     }
                else if (k == 4) { oy = 0.0f;        ox = 0.0f;        a = aref;       }
                else             { oy = offy[k - 1]; ox = offx[k - 1]; a = aff[k - 1]; }
                float sv = bilin(coarb, (float)y + kyf + oy, (float)x + kxf + ox);
                inter += a * sv;
            }
            inter = fmaxf(inter, 0.0f);
            float cd = __ldg(coarb + (size_t)y * Ww + x);
            ((float*)outp)[(size_t)b * HW + (size_t)y * Ww + x] =
                fmaxf(0.7f * cd + 0.3f * inter, 0.0f);
        }
    }
}

// ---------------- launch ------------------------------------------------------
extern "C" void kernel_launch(void* const* d_in, const int* in_sizes, int n_in,
                              void* d_out, int out_size) {
    const float* coarse  = (const float*)d_in[0];
    const float* normal  = (const float*)d_in[1];
    const float* left    = (const float*)d_in[2];
    const float* right   = (const float*)d_in[3];
    const float* conf    = (const float*)d_in[4];
    const float* conv1_w = (const float*)d_in[5];
    const float* bn1_g   = (const float*)d_in[6];
    const float* bn1_b   = (const float*)d_in[7];
    const float* bn1_m   = (const float*)d_in[8];
    const float* bn1_v   = (const float*)d_in[9];
    const float* conv2_w = (const float*)d_in[10];
    const float* bn2_g   = (const float*)d_in[11];
    const float* bn2_b   = (const float*)d_in[12];
    const float* bn2_m   = (const float*)d_in[13];
    const float* bn2_v   = (const float*)d_in[14];
    const float* conv3_w = (const float*)d_in[15];
    const float* asc     = (const float*)d_in[16];
    float* out = (float*)d_out;

    u32 *guid, *x1, *x2, *w1, *w2, *w3;
    cudaGetSymbolAddress((void**)&guid, g_guid);
    cudaGetSymbolAddress((void**)&x1, g_x1);
    cudaGetSymbolAddress((void**)&x2, g_x2);
    cudaGetSymbolAddress((void**)&w1, g_w1);
    cudaGetSymbolAddress((void**)&w2, g_w2);
    cudaGetSymbolAddress((void**)&w3, g_w3);

    // smem = NM*(K9+8)*2 (B) + 3*130*(CINP+8)*2 (A)
    const int smem1 = 32 * 152 * 2 + 3 * 130 * 24 * 2;   // 28,448
    const int smem2 = 64 * 296 * 2 + 3 * 130 * 40 * 2;   // 69,088
    const int smem3 = 32 * 584 * 2 + 3 * 130 * 72 * 2;   // 93,536
    cudaFuncSetAttribute((const void*)conv3x3_mma<12, 16, 32, 32, 16, true, false>,
                         cudaFuncAttributeMaxDynamicSharedMemorySize, smem1);
    cudaFuncSetAttribute((const void*)conv3x3_mma<32, 32, 64, 64, 32, true, false>,
                         cudaFuncAttributeMaxDynamicSharedMemorySize, smem2);
    cudaFuncSetAttribute((const void*)conv3x3_mma<64, 64, 24, 32, 16, false, true>,
                         cudaFuncAttributeMaxDynamicSharedMemorySize, smem3);

    // 0) weight prep (fp32 OIHW -> packed fp16 GEMM-B)
    prep_w<<<(32 * 72 + 64 * 144 + 32 * 288 + 255) / 256, 256>>>(conv1_w, conv2_w, conv3_w);

    // 1) warp + guidance (half2 out)
    warp_guid_k<<<(BHW + 255) / 256, 256>>>(coarse, normal, left, right, guid);

    dim3 cg(Ww / 128, Hh, Bn);   // (10, 384, 4)

    // 2) conv1 + bn + relu  (12 -> 32)
    conv3x3_mma<12, 16, 32, 32, 16, true, false><<<cg, 256, smem1>>>(
        guid, w1, bn1_g, bn1_b, bn1_m, bn1_v, nullptr, nullptr, nullptr, x1);

    // 3) conv2 + bn + relu  (32 -> 64)
    conv3x3_mma<32, 32, 64, 64, 32, true, false><<<cg, 256, smem2>>>(
        x1, w2, bn2_g, bn2_b, bn2_m, bn2_v, nullptr, nullptr, nullptr, x2);

    // 4) conv3 (64 -> 24, N padded to 32) + fused propagation -> final out
    conv3x3_mma<64, 64, 24, 32, 16, false, true><<<cg, 256, smem3>>>(
        x2, w3, nullptr, nullptr, nullptr, nullptr, conf, coarse, asc, out);
}

// round 12
// speedup vs baseline: 1.5565x; 1.0046x over previous
#include <cuda_runtime.h>
#include <cuda_fp16.h>
#include <math.h>
#include <stdint.h>

#define Bn 4
#define Hh 384
#define Ww 1280
#define HW (Hh * Ww)
#define BHW (Bn * HW)

typedef unsigned int u32;

// ---------------- scratch (device globals; half2 packed as u32) --------------
__device__ u32 g_guid[(size_t)Bn * 6 * HW];    // 12 ch as 6 half2 planes
__device__ u32 g_x1  [(size_t)Bn * 16 * HW];   // 32 ch as 16 half2 planes
__device__ u32 g_x2  [(size_t)Bn * 32 * HW];   // 64 ch as 32 half2 planes
// pre-packed fp16 GEMM-B weights: [n][9*CINP] as half2 (u32)
__device__ u32 g_w1[32 * 72];    // NM=32, K9=144
__device__ u32 g_w2[64 * 144];   // NM=64, K9=288
__device__ u32 g_w3[32 * 288];   // NM=32, K9=576

// ---------------- PTX helpers -------------------------------------------------
__device__ __forceinline__ u32 smem_u32(const void* p) {
    u32 a;
    asm("{ .reg .u64 t; cvta.to.shared.u64 t, %1; cvt.u32.u64 %0, t; }" : "=r"(a) : "l"(p));
    return a;
}
__device__ __forceinline__ void ldmA(u32* a, u32 addr) {
    asm volatile("ldmatrix.sync.aligned.m8n8.x4.shared.b16 {%0,%1,%2,%3}, [%4];"
        : "=r"(a[0]), "=r"(a[1]), "=r"(a[2]), "=r"(a[3]) : "r"(addr));
}
__device__ __forceinline__ void ldmB(u32* b, u32 addr) {
    asm volatile("ldmatrix.sync.aligned.m8n8.x2.shared.b16 {%0,%1}, [%2];"
        : "=r"(b[0]), "=r"(b[1]) : "r"(addr));
}
__device__ __forceinline__ void mma16816(float* d, const u32* a, const u32* b) {
    asm volatile("mma.sync.aligned.m16n8k16.row.col.f32.f16.f16.f32 "
        "{%0,%1,%2,%3}, {%4,%5,%6,%7}, {%8,%9}, {%0,%1,%2,%3};"
        : "+f"(d[0]), "+f"(d[1]), "+f"(d[2]), "+f"(d[3])
        : "r"(a[0]), "r"(a[1]), "r"(a[2]), "r"(a[3]), "r"(b[0]), "r"(b[1]));
}

// ---------------- weight prep: OIHW fp32 -> [n][9*CINP] fp16 pairs -----------
__device__ __forceinline__ u32 packw(const float* __restrict__ wg,
                                     int n, int j, int CIN, int CINP, int COUT) {
    int k = 2 * j, t = k / CINP, c = k % CINP;
    float v0 = 0.f, v1 = 0.f;
    if (n < COUT) {
        if (c < CIN)     v0 = __ldg(wg + ((size_t)n * CIN + c) * 9 + t);
        if (c + 1 < CIN) v1 = __ldg(wg + ((size_t)n * CIN + c + 1) * 9 + t);
    }
    __half2 h = __floats2half2_rn(v0, v1);
    return *(u32*)&h;
}
__global__ void prep_w(const float* __restrict__ w1,
                       const float* __restrict__ w2,
                       const float* __restrict__ w3) {
    int i = blockIdx.x * 256 + threadIdx.x;
    const int S1 = 32 * 72, S2 = 64 * 144, S3 = 32 * 288;
    if (i < S1) {
        g_w1[i] = packw(w1, i / 72, i % 72, 12, 16, 32);
    } else if (i < S1 + S2) {
        int q = i - S1;
        g_w2[q] = packw(w2, q / 144, q % 144, 32, 32, 64);
    } else if (i < S1 + S2 + S3) {
        int q = i - S1 - S2;
        g_w3[q] = packw(w3, q / 288, q % 288, 64, 64, 24);
    }
}

// ---------------- kernel 1: disparity warp + guidance (half2 out) ------------
__global__ void warp_guid_k(const float* __restrict__ coarse,
                            const float* __restrict__ normal,
                            const float* __restrict__ left,
                            const float* __restrict__ right,
                            u32* __restrict__ guid) {
    int idx = blockIdx.x * blockDim.x + threadIdx.x;
    if (idx >= BHW) return;
    int x = idx % Ww;
    int y = (idx / Ww) % Hh;
    int b = idx / HW;
    size_t pix = (size_t)y * Ww + x;

    float disp = __ldg(coarse + (size_t)b * HW + pix);
    float xs   = (float)x - disp;
    float x0f  = floorf(xs);
    int   x0   = (int)x0f;
    float w1   = xs - x0f;
    float wgt0 = 1.0f - w1;

    float we[3] = {0.f, 0.f, 0.f};
#pragma unroll
    for (int d = 0; d < 2; ++d) {
        int   xi = x0 + d;
        float vv = (xi >= 0 && xi < Ww) ? 1.0f : 0.0f;
        int   xc = min(max(xi, 0), Ww - 1);
        float w  = (d == 0) ? wgt0 : w1;
#pragma unroll
        for (int c = 0; c < 3; ++c)
            we[c] += w * vv * __ldg(right + ((size_t)(b * 3 + c) * Hh + y) * Ww + xc);
    }

    float v[12];
#pragma unroll
    for (int c = 0; c < 3; ++c) {
        v[c]     = __ldg(normal + (size_t)(b * 3 + c) * HW + pix);
        v[3 + c] = __ldg(left   + (size_t)(b * 3 + c) * HW + pix);
        v[6 + c] = __ldg(right  + (size_t)(b * 3 + c) * HW + pix);
        v[9 + c] = we[c] - v[3 + c];
    }
    u32* gb = guid + (size_t)b * 6 * HW + pix;
#pragma unroll
    for (int p = 0; p < 6; ++p) {
        __half2 h = __floats2half2_rn(v[2 * p], v[2 * p + 1]);
        gb[(size_t)p * HW] = *(u32*)&h;
    }
}

// ---------------- bilinear with border-validity masking ----------------------
__device__ __forceinline__ float bilin(const float* __restrict__ img, float ys, float xs) {
    float y0f = floorf(ys), x0f = floorf(xs);
    int y0 = (int)y0f, x0 = (int)x0f;
    float wy1 = ys - y0f, wx1 = xs - x0f;
    float wy0 = 1.0f - wy1, wx0 = 1.0f - wx1;
    float out = 0.0f;
#pragma unroll
    for (int dy = 0; dy < 2; ++dy) {
        int yy = y0 + dy;
        float wy = dy ? wy1 : wy0;
        bool vy = (yy >= 0 && yy < Hh);
        int yc = min(max(yy, 0), Hh - 1);
#pragma unroll
        for (int dx = 0; dx < 2; ++dx) {
            int xx = x0 + dx;
            float wx = dx ? wx1 : wx0;
            float vv = (vy && xx >= 0 && xx < Ww) ? 1.0f : 0.0f;
            int xc = min(max(xx, 0), Ww - 1);
            out += wy * wx * vv * __ldg(img + (size_t)yc * Ww + xc);
        }
    }
    return out;
}

// ---------------- mma.sync implicit-GEMM conv3x3 (R6 shape, optional fusion) --
// CTA: 128 pixels of one output row (b,y) x NM out channels. 256 thr = 8 warps,
// warp grid 4(M) x 2(N): warp tile 32 x WN.
// A staged once as [3 rows][130 x][CINP+8 ch] fp16 (no 9x im2col duplication);
// tap (ky,kx) A-fragments are ldmatrix at shifted addresses.
// B staged as [NM][9*CINP + 8] fp16 from pre-packed global.
// FUSE (conv3): transpose 24-ch outputs through smem, then threads 0-127 run the
// affinity normalization + non-local propagation epilogue and write final out.
template <int CIN, int CINP, int COUT, int NM, int WN, bool FP16OUT, bool FUSE>
__global__ void __launch_bounds__(256)
conv3x3_mma(const u32* __restrict__ in,    // half2 planes [b][CIN/2][H][W]
            const u32* __restrict__ wB,    // packed fp16 pairs [n][K9/2]
            const float* __restrict__ bng, const float* __restrict__ bnb,
            const float* __restrict__ bnm, const float* __restrict__ bnv,
            const float* __restrict__ conf, const float* __restrict__ coarse,
            const float* __restrict__ ascp,
            void* __restrict__ outp) {
    constexpr int K9   = 9 * CINP;
    constexpr int KP   = K9 + 8;       // B row stride (fp16), conflict-free
    constexpr int ASTR = CINP + 8;     // A x-stride (fp16), conflict-free
    constexpr int PP   = CINP / 2;
    constexpr int NI   = WN / 8;

    extern __shared__ char smem[];
    __half* sB = (__half*)smem;                         // NM * KP
    __half* sA = (__half*)(smem + (size_t)NM * KP * 2); // 3*130*ASTR

    const int tid = threadIdx.x;
    const int x0 = blockIdx.x * 128, y = blockIdx.y, b = blockIdx.z;

    // ---- stage B (u32 copy of packed fp16 pairs) ----
    for (int i = tid; i < NM * (K9 / 2); i += 256) {
        int n = i / (K9 / 2), j = i % (K9 / 2);
        *(u32*)(sB + (size_t)n * KP + 2 * j) = __ldg(wB + i);
    }
    // ---- stage A: 3 rows x 130 x CINP fp16 (pad channels / borders zeroed) --
    const u32* inb = in + (size_t)b * (CIN / 2) * HW;
    for (int i = tid; i < 3 * PP * 130; i += 256) {
        int xloc = i % 130;
        int rp   = i / 130;
        int r = rp / PP, p = rp % PP;
        int yy = y + r - 1, xx = x0 - 1 + xloc;
        u32 v = 0;
        if (p < CIN / 2 && yy >= 0 && yy < Hh && (unsigned)xx < (unsigned)Ww)
            v = __ldg(inb + (size_t)p * HW + (size_t)yy * Ww + xx);
        *(u32*)(sA + ((size_t)(r * 130 + xloc)) * ASTR + 2 * p) = v;
    }
    __syncthreads();

    const int lane = tid & 31, wid = tid >> 5;
    const int wm = wid & 3, wn = wid >> 2;
    const int m0 = wm * 32;

    const u32 aBase = smem_u32(sA);
    const u32 bBase = smem_u32(sB);
    const int rowA = lane & 15;
    const int kofA = (lane >> 4) * 8;
    const int rowB = lane & 7;
    const int kofB = ((lane >> 3) & 1) * 8;

    float d[2][NI][4];
#pragma unroll
    for (int mi = 0; mi < 2; ++mi)
#pragma unroll
        for (int ni = 0; ni < NI; ++ni)
#pragma unroll
            for (int c = 0; c < 4; ++c) d[mi][ni][c] = 0.0f;

#pragma unroll
    for (int t = 0; t < 9; ++t) {
        const int ky = t / 3, kx = t % 3;
        u32 aRow0 = aBase + (u32)(((ky * 130 + m0 + rowA + kx) * ASTR + kofA) * 2);
        u32 aRow1 = aRow0 + 16 * ASTR * 2;
        u32 bRow  = bBase + (u32)((((wn * WN + rowB) * KP) + t * CINP + kofB) * 2);
#pragma unroll
        for (int kk = 0; kk < CINP / 16; ++kk) {
            u32 a0[4], a1[4];
            ldmA(a0, aRow0 + kk * 32);
            ldmA(a1, aRow1 + kk * 32);
#pragma unroll
            for (int ni = 0; ni < NI; ++ni) {
                u32 bb[2];
                ldmB(bb, bRow + (u32)(ni * 8 * KP * 2) + kk * 32);
                mma16816(d[0][ni], a0, bb);
                mma16816(d[1][ni], a1, bb);
            }
        }
    }

    const int r4 = lane >> 2, c4 = lane & 3;

    if (!FUSE) {
        // ---- BN + ReLU epilogue, half2 planar out ----
#pragma unroll
        for (int ni = 0; ni < NI; ++ni) {
            int ch = wn * WN + ni * 8 + c4 * 2;
            float s0 = __ldg(bng + ch)     * rsqrtf(__ldg(bnv + ch) + 1e-5f);
            float t0 = __ldg(bnb + ch)     - __ldg(bnm + ch) * s0;
            float s1 = __ldg(bng + ch + 1) * rsqrtf(__ldg(bnv + ch + 1) + 1e-5f);
            float t1 = __ldg(bnb + ch + 1) - __ldg(bnm + ch + 1) * s1;
#pragma unroll
            for (int mi = 0; mi < 2; ++mi) {
                int x = x0 + m0 + mi * 16 + r4;
                u32* oh = (u32*)outp + (size_t)b * (COUT / 2) * HW
                                     + (size_t)(ch >> 1) * HW + (size_t)y * Ww;
                float v00 = fmaxf(d[mi][ni][0] * s0 + t0, 0.f);
                float v01 = fmaxf(d[mi][ni][1] * s1 + t1, 0.f);
                float v10 = fmaxf(d[mi][ni][2] * s0 + t0, 0.f);
                float v11 = fmaxf(d[mi][ni][3] * s1 + t1, 0.f);
                __half2 h0 = __floats2half2_rn(v00, v01);
                __half2 h1 = __floats2half2_rn(v10, v11);
                oh[x]     = *(u32*)&h0;
                oh[x + 8] = *(u32*)&h1;
            }
        }
    } else {
        // ---- fused propagation epilogue (conv3 path, 8 warps) ----
        __syncthreads();                       // mainloop smem reads done
        float* s_t = (float*)smem;             // [128 px][25] transpose buffer
#pragma unroll
        for (int ni = 0; ni < NI; ++ni) {
            int ch = wn * WN + ni * 8 + c4 * 2;
            if (ch < 24) {
#pragma unroll
                for (int mi = 0; mi < 2; ++mi) {
                    int px = m0 + mi * 16 + r4;
                    s_t[px * 25 + ch]           = d[mi][ni][0];
                    s_t[px * 25 + ch + 1]       = d[mi][ni][1];
                    s_t[(px + 8) * 25 + ch]     = d[mi][ni][2];
                    s_t[(px + 8) * 25 + ch + 1] = d[mi][ni][3];
                }
            }
        }
        __syncthreads();

        if (tid < 128) {
            const int px = tid;                // 0..127
            const int x = x0 + px;
            const float asc = __ldg(ascp) + 1e-8f;
            const float* confb = conf + (size_t)b * HW;
            const float* coarb = coarse + (size_t)b * HW;
            const float* row = s_t + px * 25;

            float offy[8], offx[8], aff[8];
#pragma unroll
            for (int n = 0; n < 8; ++n) {
                offy[n] = row[2 * n];
                offx[n] = row[2 * n + 1];
                float a = tanhf(row[16 + n]) / asc;
                float ca = bilin(confb, (float)y + offy[n], (float)x + offx[n]);
                aff[n] = a * ca;
            }
            float s = 1e-4f;
#pragma unroll
            for (int n = 0; n < 8; ++n) s += fabsf(aff[n]);
            s = fmaxf(s, 1.0f);
            float suma = 0.0f;
#pragma unroll
            for (int n = 0; n < 8; ++n) { aff[n] /= s; suma += aff[n]; }
            float aref = 1.0f - suma;

            float inter = 0.0f;
#pragma unroll
            for (int k = 0; k < 9; ++k) {
                float kyf = (float)(k / 3) - 1.0f;
                float kxf = (float)(k % 3) - 1.0f;
                float oy, ox, a;
                if (k < 4)       { oy = offy[k];     ox = offx[k];     a = aff[k];     }
                else if (k == 4) { oy = 0.0f;        ox = 0.0f;        a = aref;       }
                else             { oy = offy[k - 1]; ox = offx[k - 1]; a = aff[k - 1]; }
                float sv = bilin(coarb, (float)y + kyf + oy, (float)x + kxf + ox);
                inter += a * sv;
            }
            inter = fmaxf(inter, 0.0f);
            float cd = __ldg(coarb + (size_t)y * Ww + x);
            ((float*)outp)[(size_t)b * HW + (size_t)y * Ww + x] =
                fmaxf(0.7f * cd + 0.3f * inter, 0.0f);
        }
    }
}

// ---------------- launch ------------------------------------------------------
extern "C" void kernel_launch(void* const* d_in, const int* in_sizes, int n_in,
                              void* d_out, int out_size) {
    const float* coarse  = (const float*)d_in[0];
    const float* normal  = (const float*)d_in[1];
    const float* left    = (const float*)d_in[2];
    const float* right   = (const float*)d_in[3];
    const float* conf    = (const float*)d_in[4];
    const float* conv1_w = (const float*)d_in[5];
    const float* bn1_g   = (const float*)d_in[6];
    const float* bn1_b   = (const float*)d_in[7];
    const float* bn1_m   = (const float*)d_in[8];
    const float* bn1_v   = (const float*)d_in[9];
    const float* conv2_w = (const float*)d_in[10];
    const float* bn2_g   = (const float*)d_in[11];
    const float* bn2_b   = (const float*)d_in[12];
    const float* bn2_m   = (const float*)d_in[13];
    const float* bn2_v   = (const float*)d_in[14];
    const float* conv3_w = (const float*)d_in[15];
    const float* asc     = (const float*)d_in[16];
    float* out = (float*)d_out;

    u32 *guid, *x1, *x2, *w1, *w2, *w3;
    cudaGetSymbolAddress((void**)&guid, g_guid);
    cudaGetSymbolAddress((void**)&x1, g_x1);
    cudaGetSymbolAddress((void**)&x2, g_x2);
    cudaGetSymbolAddress((void**)&w1, g_w1);
    cudaGetSymbolAddress((void**)&w2, g_w2);
    cudaGetSymbolAddress((void**)&w3, g_w3);

    // smem = NM*(K9+8)*2 (B) + 3*130*(CINP+8)*2 (A)
    const int smem1 = 32 * 152 * 2 + 3 * 130 * 24 * 2;   // 28,448
    const int smem2 = 64 * 296 * 2 + 3 * 130 * 40 * 2;   // 69,088
    const int smem3 = 32 * 584 * 2 + 3 * 130 * 72 * 2;   // 93,536
    cudaFuncSetAttribute((const void*)conv3x3_mma<12, 16, 32, 32, 16, true, false>,
                         cudaFuncAttributeMaxDynamicSharedMemorySize, smem1);
    cudaFuncSetAttribute((const void*)conv3x3_mma<32, 32, 64, 64, 32, true, false>,
                         cudaFuncAttributeMaxDynamicSharedMemorySize, smem2);
    cudaFuncSetAttribute((const void*)conv3x3_mma<64, 64, 24, 32, 16, false, true>,
                         cudaFuncAttributeMaxDynamicSharedMemorySize, smem3);

    // 0) weight prep (fp32 OIHW -> packed fp16 GEMM-B)
    prep_w<<<(32 * 72 + 64 * 144 + 32 * 288 + 255) / 256, 256>>>(conv1_w, conv2_w, conv3_w);

    // 1) warp + guidance (half2 out)
    warp_guid_k<<<(BHW + 255) / 256, 256>>>(coarse, normal, left, right, guid);

    dim3 cg(Ww / 128, Hh, Bn);   // (10, 384, 4)

    // 2) conv1 + bn + relu  (12 -> 32)
    conv3x3_mma<12, 16, 32, 32, 16, true, false><<<cg, 256, smem1>>>(
        guid, w1, bn1_g, bn1_b, bn1_m, bn1_v, nullptr, nullptr, nullptr, x1);

    // 3) conv2 + bn + relu  (32 -> 64)
    conv3x3_mma<32, 32, 64, 64, 32, true, false><<<cg, 256, smem2>>>(
        x1, w2, bn2_g, bn2_b, bn2_m, bn2_v, nullptr, nullptr, nullptr, x2);

    // 4) conv3 (64 -> 24, N padded to 32) + fused propagation -> final out
    conv3x3_mma<64, 64, 24, 32, 16, false, true><<<cg, 256, smem3>>>(
        x2, w3, nullptr, nullptr, nullptr, nullptr, conf, coarse, asc, out);
}

// round 13
// speedup vs baseline: 1.6875x; 1.0842x over previous
#include <cuda_runtime.h>
#include <cuda_fp16.h>
#include <math.h>
#include <stdint.h>

#define Bn 4
#define Hh 384
#define Ww 1280
#define HW (Hh * Ww)
#define BHW (Bn * HW)

typedef unsigned int u32;

// ---------------- scratch (device globals; half2 packed as u32) --------------
__device__ u32   g_x1[(size_t)Bn * 16 * HW];   // 32 ch as 16 half2 planes
__device__ u32   g_x2[(size_t)Bn * 32 * HW];   // 64 ch as 32 half2 planes
__device__ float g_oa[(size_t)Bn * 24 * HW];   // fp32 planar
// pre-packed fp16 GEMM-B weights: [n][9*CINP] as half2 (u32)
__device__ u32   g_w1[32 * 72];    // NM=32, K9=144
__device__ u32   g_w2[64 * 144];   // NM=64, K9=288
__device__ u32   g_w3[32 * 288];   // NM=32, K9=576

// ---------------- PTX helpers -------------------------------------------------
__device__ __forceinline__ u32 smem_u32(const void* p) {
    u32 a;
    asm("{ .reg .u64 t; cvta.to.shared.u64 t, %1; cvt.u32.u64 %0, t; }" : "=r"(a) : "l"(p));
    return a;
}
__device__ __forceinline__ void ldmA(u32* a, u32 addr) {
    asm volatile("ldmatrix.sync.aligned.m8n8.x4.shared.b16 {%0,%1,%2,%3}, [%4];"
        : "=r"(a[0]), "=r"(a[1]), "=r"(a[2]), "=r"(a[3]) : "r"(addr));
}
__device__ __forceinline__ void ldmB(u32* b, u32 addr) {
    asm volatile("ldmatrix.sync.aligned.m8n8.x2.shared.b16 {%0,%1}, [%2];"
        : "=r"(b[0]), "=r"(b[1]) : "r"(addr));
}
__device__ __forceinline__ void mma16816(float* d, const u32* a, const u32* b) {
    asm volatile("mma.sync.aligned.m16n8k16.row.col.f32.f16.f16.f32 "
        "{%0,%1,%2,%3}, {%4,%5,%6,%7}, {%8,%9}, {%0,%1,%2,%3};"
        : "+f"(d[0]), "+f"(d[1]), "+f"(d[2]), "+f"(d[3])
        : "r"(a[0]), "r"(a[1]), "r"(a[2]), "r"(a[3]), "r"(b[0]), "r"(b[1]));
}

// ---------------- weight prep: OIHW fp32 -> [n][9*CINP] fp16 pairs -----------
__device__ __forceinline__ u32 packw(const float* __restrict__ wg,
                                     int n, int j, int CIN, int CINP, int COUT) {
    int k = 2 * j, t = k / CINP, c = k % CINP;
    float v0 = 0.f, v1 = 0.f;
    if (n < COUT) {
        if (c < CIN)     v0 = __ldg(wg + ((size_t)n * CIN + c) * 9 + t);
        if (c + 1 < CIN) v1 = __ldg(wg + ((size_t)n * CIN + c + 1) * 9 + t);
    }
    __half2 h = __floats2half2_rn(v0, v1);
    return *(u32*)&h;
}
__global__ void prep_w(const float* __restrict__ w1,
                       const float* __restrict__ w2,
                       const float* __restrict__ w3) {
    int i = blockIdx.x * 256 + threadIdx.x;
    const int S1 = 32 * 72, S2 = 64 * 144, S3 = 32 * 288;
    if (i < S1) {
        g_w1[i] = packw(w1, i / 72, i % 72, 12, 16, 32);
    } else if (i < S1 + S2) {
        int q = i - S1;
        g_w2[q] = packw(w2, q / 144, q % 144, 32, 32, 64);
    } else if (i < S1 + S2 + S3) {
        int q = i - S1 - S2;
        g_w3[q] = packw(w3, q / 288, q % 288, 64, 64, 24);
    }
}

// ---------------- bilinear with border-validity masking ----------------------
__device__ __forceinline__ float bilin(const float* __restrict__ img, float ys, float xs) {
    float y0f = floorf(ys), x0f = floorf(xs);
    int y0 = (int)y0f, x0 = (int)x0f;
    float wy1 = ys - y0f, wx1 = xs - x0f;
    float wy0 = 1.0f - wy1, wx0 = 1.0f - wx1;
    float out = 0.0f;
#pragma unroll
    for (int dy = 0; dy < 2; ++dy) {
        int yy = y0 + dy;
        float wy = dy ? wy1 : wy0;
        bool vy = (yy >= 0 && yy < Hh);
        int yc = min(max(yy, 0), Hh - 1);
#pragma unroll
        for (int dx = 0; dx < 2; ++dx) {
            int xx = x0 + dx;
            float wx = dx ? wx1 : wx0;
            float vv = (vy && xx >= 0 && xx < Ww) ? 1.0f : 0.0f;
            int xc = min(max(xx, 0), Ww - 1);
            out += wy * wx * vv * __ldg(img + (size_t)yc * Ww + xc);
        }
    }
    return out;
}

// ---------------- mma.sync implicit-GEMM conv3x3 ------------------------------
// CTA: 128 pixels of one output row (b,y) x NM out channels. 256 thr = 8 warps,
// warp grid 4(M) x 2(N): warp tile 32 x WN.
// A staged once as [3 rows][130 x][CINP+8 ch] fp16 (no 9x im2col duplication);
// tap (ky,kx) A-fragments are ldmatrix at shifted addresses.
// B staged as [NMAX][9*CINP + 8] fp16 from pre-packed global; n-groups >= NMAX
// are skipped in the mainloop (removes conv3's N-padding work).
// GUIDIN (conv1): A-staging computes the disparity-warp + guidance inline from
// the raw inputs (no global guid round-trip).
template <int CIN, int CINP, int COUT, int NM, int WN, int NMAX,
          bool FP16OUT, bool GUIDIN>
__global__ void __launch_bounds__(256)
conv3x3_mma(const u32* __restrict__ in,    // half2 planes [b][CIN/2][H][W]
            const u32* __restrict__ wB,    // packed fp16 pairs [n][K9/2]
            const float* __restrict__ bng, const float* __restrict__ bnb,
            const float* __restrict__ bnm, const float* __restrict__ bnv,
            const float* __restrict__ coarse, const float* __restrict__ normal,
            const float* __restrict__ left,   const float* __restrict__ right,
            void* __restrict__ outp) {
    constexpr int K9   = 9 * CINP;
    constexpr int KP   = K9 + 8;       // B row stride (fp16), conflict-free
    constexpr int ASTR = CINP + 8;     // A x-stride (fp16), conflict-free
    constexpr int PP   = CINP / 2;
    constexpr int NI   = WN / 8;

    extern __shared__ char smem[];
    __half* sB = (__half*)smem;                           // NMAX * KP
    __half* sA = (__half*)(smem + (size_t)NMAX * KP * 2); // 3*130*ASTR

    const int tid = threadIdx.x;
    const int x0 = blockIdx.x * 128, y = blockIdx.y, b = blockIdx.z;

    // ---- stage B (u32 copy of packed fp16 pairs) ----
    for (int i = tid; i < NMAX * (K9 / 2); i += 256) {
        int n = i / (K9 / 2), j = i % (K9 / 2);
        *(u32*)(sB + (size_t)n * KP + 2 * j) = __ldg(wB + i);
    }

    if (GUIDIN) {
        // ---- stage A with inline warp + guidance (conv1, CINP=16) ----
        for (int i = tid; i < 3 * 130; i += 256) {
            int r = i / 130, xloc = i % 130;
            int yy = y + r - 1, xx = x0 - 1 + xloc;
            u32 pk[8] = {0, 0, 0, 0, 0, 0, 0, 0};
            if (yy >= 0 && yy < Hh && (unsigned)xx < (unsigned)Ww) {
                size_t pix = (size_t)yy * Ww + xx;
                float disp = __ldg(coarse + (size_t)b * HW + pix);
                float xsf  = (float)xx - disp;
                float x0f  = floorf(xsf);
                int   xi0  = (int)x0f;
                float w1   = xsf - x0f;
                float w0   = 1.0f - w1;
                float we[3] = {0.f, 0.f, 0.f};
#pragma unroll
                for (int d = 0; d < 2; ++d) {
                    int   xi = xi0 + d;
                    float vv = (xi >= 0 && xi < Ww) ? 1.0f : 0.0f;
                    int   xc = min(max(xi, 0), Ww - 1);
                    float w  = (d == 0) ? w0 : w1;
#pragma unroll
                    for (int c = 0; c < 3; ++c)
                        we[c] += w * vv *
                            __ldg(right + ((size_t)(b * 3 + c) * Hh + yy) * Ww + xc);
                }
                float v[12];
#pragma unroll
                for (int c = 0; c < 3; ++c) {
                    v[c]     = __ldg(normal + (size_t)(b * 3 + c) * HW + pix);
                    v[3 + c] = __ldg(left   + (size_t)(b * 3 + c) * HW + pix);
                    v[6 + c] = __ldg(right  + (size_t)(b * 3 + c) * HW + pix);
                    v[9 + c] = we[c] - v[3 + c];
                }
#pragma unroll
                for (int p = 0; p < 6; ++p) {
                    __half2 h = __floats2half2_rn(v[2 * p], v[2 * p + 1]);
                    pk[p] = *(u32*)&h;
                }
            }
            u32* dst = (u32*)(sA + (size_t)(r * 130 + xloc) * ASTR);
            *(uint4*)dst       = make_uint4(pk[0], pk[1], pk[2], pk[3]);
            *(uint4*)(dst + 4) = make_uint4(pk[4], pk[5], pk[6], pk[7]);
        }
    } else {
        // ---- stage A: 3 rows x 130 x CINP fp16 ----
        const u32* inb = in + (size_t)b * (CIN / 2) * HW;
        for (int i = tid; i < 3 * PP * 130; i += 256) {
            int xloc = i % 130;
            int rp   = i / 130;
            int r = rp / PP, p = rp % PP;
            int yy = y + r - 1, xx = x0 - 1 + xloc;
            u32 v = 0;
            if (p < CIN / 2 && yy >= 0 && yy < Hh && (unsigned)xx < (unsigned)Ww)
                v = __ldg(inb + (size_t)p * HW + (size_t)yy * Ww + xx);
            *(u32*)(sA + ((size_t)(r * 130 + xloc)) * ASTR + 2 * p) = v;
        }
    }
    __syncthreads();

    const int lane = tid & 31, wid = tid >> 5;
    const int wm = wid & 3, wn = wid >> 2;
    const int m0 = wm * 32;

    const u32 aBase = smem_u32(sA);
    const u32 bBase = smem_u32(sB);
    const int rowA = lane & 15;
    const int kofA = (lane >> 4) * 8;
    const int rowB = lane & 7;
    const int kofB = ((lane >> 3) & 1) * 8;

    float d[2][NI][4];
#pragma unroll
    for (int mi = 0; mi < 2; ++mi)
#pragma unroll
        for (int ni = 0; ni < NI; ++ni)
#pragma unroll
            for (int c = 0; c < 4; ++c) d[mi][ni][c] = 0.0f;

#pragma unroll
    for (int t = 0; t < 9; ++t) {
        const int ky = t / 3, kx = t % 3;
        u32 aRow0 = aBase + (u32)(((ky * 130 + m0 + rowA + kx) * ASTR + kofA) * 2);
        u32 aRow1 = aRow0 + 16 * ASTR * 2;
        u32 bRow  = bBase + (u32)((((wn * WN + rowB) * KP) + t * CINP + kofB) * 2);
#pragma unroll
        for (int kk = 0; kk < CINP / 16; ++kk) {
            u32 a0[4], a1[4];
            ldmA(a0, aRow0 + kk * 32);
            ldmA(a1, aRow1 + kk * 32);
#pragma unroll
            for (int ni = 0; ni < NI; ++ni) {
                if (NMAX == NM || wn * WN + ni * 8 < NMAX) {
                    u32 bb[2];
                    ldmB(bb, bRow + (u32)(ni * 8 * KP * 2) + kk * 32);
                    mma16816(d[0][ni], a0, bb);
                    mma16816(d[1][ni], a1, bb);
                }
            }
        }
    }

    // ---- epilogue ----
    const int r4 = lane >> 2, c4 = lane & 3;
#pragma unroll
    for (int ni = 0; ni < NI; ++ni) {
        int ch = wn * WN + ni * 8 + c4 * 2;
        if (FP16OUT) {
            float s0 = __ldg(bng + ch)     * rsqrtf(__ldg(bnv + ch) + 1e-5f);
            float t0 = __ldg(bnb + ch)     - __ldg(bnm + ch) * s0;
            float s1 = __ldg(bng + ch + 1) * rsqrtf(__ldg(bnv + ch + 1) + 1e-5f);
            float t1 = __ldg(bnb + ch + 1) - __ldg(bnm + ch + 1) * s1;
#pragma unroll
            for (int mi = 0; mi < 2; ++mi) {
                int x = x0 + m0 + mi * 16 + r4;
                u32* oh = (u32*)outp + (size_t)b * (COUT / 2) * HW
                                     + (size_t)(ch >> 1) * HW + (size_t)y * Ww;
                float v00 = fmaxf(d[mi][ni][0] * s0 + t0, 0.f);
                float v01 = fmaxf(d[mi][ni][1] * s1 + t1, 0.f);
                float v10 = fmaxf(d[mi][ni][2] * s0 + t0, 0.f);
                float v11 = fmaxf(d[mi][ni][3] * s1 + t1, 0.f);
                __half2 h0 = __floats2half2_rn(v00, v01);
                __half2 h1 = __floats2half2_rn(v10, v11);
                oh[x]     = *(u32*)&h0;
                oh[x + 8] = *(u32*)&h1;
            }
        } else if (ch < COUT) {
#pragma unroll
            for (int mi = 0; mi < 2; ++mi) {
                int x = x0 + m0 + mi * 16 + r4;
                float* of = (float*)outp + (size_t)b * COUT * HW + (size_t)y * Ww;
                of[(size_t)ch * HW + x]           = d[mi][ni][0];
                of[(size_t)(ch + 1) * HW + x]     = d[mi][ni][1];
                of[(size_t)ch * HW + x + 8]       = d[mi][ni][2];
                of[(size_t)(ch + 1) * HW + x + 8] = d[mi][ni][3];
            }
        }
    }
}

// ---------------- kernel 5: affinity normalization + propagation -------------
__global__ void propagate_k(const float* __restrict__ oa,
                            const float* __restrict__ conf,
                            const float* __restrict__ coarse,
                            const float* __restrict__ ascp,
                            float* __restrict__ out) {
    int idx = blockIdx.x * blockDim.x + threadIdx.x;
    if (idx >= BHW) return;
    int x = idx % Ww;
    int y = (idx / Ww) % Hh;
    int b = idx / HW;

    const float asc = __ldg(ascp) + 1e-8f;
    const float* oab   = oa + (size_t)b * 24 * HW + (size_t)y * Ww + x;
    const float* confb = conf + (size_t)b * HW;
    const float* coarb = coarse + (size_t)b * HW;

    float offy[8], offx[8], aff[8];
#pragma unroll
    for (int n = 0; n < 8; ++n) {
        offy[n] = __ldg(oab + (size_t)(2 * n) * HW);
        offx[n] = __ldg(oab + (size_t)(2 * n + 1) * HW);
        float a = tanhf(__ldg(oab + (size_t)(16 + n) * HW)) / asc;
        float ca = bilin(confb, (float)y + offy[n], (float)x + offx[n]);
        aff[n] = a * ca;
    }
    float s = 1e-4f;
#pragma unroll
    for (int n = 0; n < 8; ++n) s += fabsf(aff[n]);
    s = fmaxf(s, 1.0f);
    float suma = 0.0f;
#pragma unroll
    for (int n = 0; n < 8; ++n) { aff[n] /= s; suma += aff[n]; }
    float aref = 1.0f - suma;

    float inter = 0.0f;
#pragma unroll
    for (int k = 0; k < 9; ++k) {
        float ky = (float)(k / 3) - 1.0f;
        float kx = (float)(k % 3) - 1.0f;
        float oy, ox, a;
        if (k < 4)       { oy = offy[k];     ox = offx[k];     a = aff[k];     }
        else if (k == 4) { oy = 0.0f;        ox = 0.0f;        a = aref;       }
        else             { oy = offy[k - 1]; ox = offx[k - 1]; a = aff[k - 1]; }
        float sv = bilin(coarb, (float)y + ky + oy, (float)x + kx + ox);
        inter += a * sv;
    }
    inter = fmaxf(inter, 0.0f);
    float cd = __ldg(coarb + (size_t)y * Ww + x);
    out[idx] = fmaxf(0.7f * cd + 0.3f * inter, 0.0f);
}

// ---------------- launch ------------------------------------------------------
extern "C" void kernel_launch(void* const* d_in, const int* in_sizes, int n_in,
                              void* d_out, int out_size) {
    const float* coarse  = (const float*)d_in[0];
    const float* normal  = (const float*)d_in[1];
    const float* left    = (const float*)d_in[2];
    const float* right   = (const float*)d_in[3];
    const float* conf    = (const float*)d_in[4];
    const float* conv1_w = (const float*)d_in[5];
    const float* bn1_g   = (const float*)d_in[6];
    const float* bn1_b   = (const float*)d_in[7];
    const float* bn1_m   = (const float*)d_in[8];
    const float* bn1_v   = (const float*)d_in[9];
    const float* conv2_w = (const float*)d_in[10];
    const float* bn2_g   = (const float*)d_in[11];
    const float* bn2_b   = (const float*)d_in[12];
    const float* bn2_m   = (const float*)d_in[13];
    const float* bn2_v   = (const float*)d_in[14];
    const float* conv3_w = (const float*)d_in[15];
    const float* asc     = (const float*)d_in[16];
    float* out = (float*)d_out;

    u32 *x1, *x2, *w1, *w2, *w3;
    float* oa;
    cudaGetSymbolAddress((void**)&x1, g_x1);
    cudaGetSymbolAddress((void**)&x2, g_x2);
    cudaGetSymbolAddress((void**)&oa, g_oa);
    cudaGetSymbolAddress((void**)&w1, g_w1);
    cudaGetSymbolAddress((void**)&w2, g_w2);
    cudaGetSymbolAddress((void**)&w3, g_w3);

    // smem = NMAX*(K9+8)*2 (B) + 3*130*(CINP+8)*2 (A)
    const int smem1 = 32 * 152 * 2 + 3 * 130 * 24 * 2;   // 28,448
    const int smem2 = 64 * 296 * 2 + 3 * 130 * 40 * 2;   // 69,088
    const int smem3 = 24 * 584 * 2 + 3 * 130 * 72 * 2;   // 84,192
    cudaFuncSetAttribute(
        (const void*)conv3x3_mma<12, 16, 32, 32, 16, 32, true, true>,
        cudaFuncAttributeMaxDynamicSharedMemorySize, smem1);
    cudaFuncSetAttribute(
        (const void*)conv3x3_mma<32, 32, 64, 64, 32, 64, true, false>,
        cudaFuncAttributeMaxDynamicSharedMemorySize, smem2);
    cudaFuncSetAttribute(
        (const void*)conv3x3_mma<64, 64, 24, 32, 16, 24, false, false>,
        cudaFuncAttributeMaxDynamicSharedMemorySize, smem3);

    // 0) weight prep (fp32 OIHW -> packed fp16 GEMM-B)
    prep_w<<<(32 * 72 + 64 * 144 + 32 * 288 + 255) / 256, 256>>>(conv1_w, conv2_w, conv3_w);

    dim3 cg(Ww / 128, Hh, Bn);   // (10, 384, 4)

    // 1+2) conv1 + bn + relu (12 -> 32) with inline warp+guidance staging
    conv3x3_mma<12, 16, 32, 32, 16, 32, true, true><<<cg, 256, smem1>>>(
        nullptr, w1, bn1_g, bn1_b, bn1_m, bn1_v,
        coarse, normal, left, right, x1);

    // 3) conv2 + bn + relu  (32 -> 64)
    conv3x3_mma<32, 32, 64, 64, 32, 64, true, false><<<cg, 256, smem2>>>(
        x1, w2, bn2_g, bn2_b, bn2_m, bn2_v,
        nullptr, nullptr, nullptr, nullptr, x2);

    // 4) conv3 (64 -> 24, no N padding work: NMAX=24)
    conv3x3_mma<64, 64, 24, 32, 16, 24, false, false><<<cg, 256, smem3>>>(
        x2, w3, nullptr, nullptr, nullptr, nullptr,
        nullptr, nullptr, nullptr, nullptr, oa);

    // 5) propagation epilogue
    propagate_k<<<(BHW + 255) / 256, 256>>>(oa, conf, coarse, asc, out);
}

// round 14
// speedup vs baseline: 1.9830x; 1.1751x over previous
#include <cuda_runtime.h>
#include <cuda_fp16.h>
#include <math.h>
#include <stdint.h>

#define Bn 4
#define Hh 384
#define Ww 1280
#define HW (Hh * Ww)
#define BHW (Bn * HW)

typedef unsigned int u32;

// ---------------- scratch (device globals; half2 packed as u32) --------------
__device__ u32   g_x1[(size_t)Bn * 16 * HW];   // 32 ch as 16 half2 planes
__device__ u32   g_x2[(size_t)Bn * 32 * HW];   // 64 ch as 32 half2 planes
__device__ float g_oa[(size_t)Bn * 24 * HW];   // fp32 planar
// pre-packed fp16 GEMM-B weights: [n][9*CINP] as half2 (u32)
__device__ u32   g_w1[32 * 72];    // NM=32, K9=144
__device__ u32   g_w2[64 * 144];   // NM=64, K9=288
__device__ u32   g_w3[32 * 288];   // NM=32, K9=576

// ---------------- PTX helpers -------------------------------------------------
__device__ __forceinline__ u32 smem_u32(const void* p) {
    u32 a;
    asm("{ .reg .u64 t; cvta.to.shared.u64 t, %1; cvt.u32.u64 %0, t; }" : "=r"(a) : "l"(p));
    return a;
}
__device__ __forceinline__ void ldmA(u32* a, u32 addr) {
    asm volatile("ldmatrix.sync.aligned.m8n8.x4.shared.b16 {%0,%1,%2,%3}, [%4];"
        : "=r"(a[0]), "=r"(a[1]), "=r"(a[2]), "=r"(a[3]) : "r"(addr));
}
__device__ __forceinline__ void ldmB(u32* b, u32 addr) {
    asm volatile("ldmatrix.sync.aligned.m8n8.x2.shared.b16 {%0,%1}, [%2];"
        : "=r"(b[0]), "=r"(b[1]) : "r"(addr));
}
__device__ __forceinline__ void mma16816(float* d, const u32* a, const u32* b) {
    asm volatile("mma.sync.aligned.m16n8k16.row.col.f32.f16.f16.f32 "
        "{%0,%1,%2,%3}, {%4,%5,%6,%7}, {%8,%9}, {%0,%1,%2,%3};"
        : "+f"(d[0]), "+f"(d[1]), "+f"(d[2]), "+f"(d[3])
        : "r"(a[0]), "r"(a[1]), "r"(a[2]), "r"(a[3]), "r"(b[0]), "r"(b[1]));
}

// ---------------- weight prep: OIHW fp32 -> [n][9*CINP] fp16 pairs -----------
__device__ __forceinline__ u32 packw(const float* __restrict__ wg,
                                     int n, int j, int CIN, int CINP, int COUT) {
    int k = 2 * j, t = k / CINP, c = k % CINP;
    float v0 = 0.f, v1 = 0.f;
    if (n < COUT) {
        if (c < CIN)     v0 = __ldg(wg + ((size_t)n * CIN + c) * 9 + t);
        if (c + 1 < CIN) v1 = __ldg(wg + ((size_t)n * CIN + c + 1) * 9 + t);
    }
    __half2 h = __floats2half2_rn(v0, v1);
    return *(u32*)&h;
}
__global__ void prep_w(const float* __restrict__ w1,
                       const float* __restrict__ w2,
                       const float* __restrict__ w3) {
    int i = blockIdx.x * 256 + threadIdx.x;
    const int S1 = 32 * 72, S2 = 64 * 144, S3 = 32 * 288;
    if (i < S1) {
        g_w1[i] = packw(w1, i / 72, i % 72, 12, 16, 32);
    } else if (i < S1 + S2) {
        int q = i - S1;
        g_w2[q] = packw(w2, q / 144, q % 144, 32, 32, 64);
    } else if (i < S1 + S2 + S3) {
        int q = i - S1 - S2;
        g_w3[q] = packw(w3, q / 288, q % 288, 64, 64, 24);
    }
}

// ---------------- bilinear with border-validity masking ----------------------
__device__ __forceinline__ float bilin(const float* __restrict__ img, float ys, float xs) {
    float y0f = floorf(ys), x0f = floorf(xs);
    int y0 = (int)y0f, x0 = (int)x0f;
    float wy1 = ys - y0f, wx1 = xs - x0f;
    float wy0 = 1.0f - wy1, wx0 = 1.0f - wx1;
    float out = 0.0f;
#pragma unroll
    for (int dy = 0; dy < 2; ++dy) {
        int yy = y0 + dy;
        float wy = dy ? wy1 : wy0;
        bool vy = (yy >= 0 && yy < Hh);
        int yc = min(max(yy, 0), Hh - 1);
#pragma unroll
        for (int dx = 0; dx < 2; ++dx) {
            int xx = x0 + dx;
            float wx = dx ? wx1 : wx0;
            float vv = (vy && xx >= 0 && xx < Ww) ? 1.0f : 0.0f;
            int xc = min(max(xx, 0), Ww - 1);
            out += wy * wx * vv * __ldg(img + (size_t)yc * Ww + xc);
        }
    }
    return out;
}

// ---------------- mma.sync implicit-GEMM conv3x3 ------------------------------
// CTA: NROWS output rows x 128 px of (b, ybase..) x NM out channels, 8 warps.
// Warp grid 4(M) x 2(N); warp M-tile = MI*16 px where MI = 2*NROWS.
// NROWS=2: warps 0,1 -> row 0 (x 0-63 / 64-127), warps 2,3 -> row 1; the two
// rows share a 4-row halo, and B staging is amortized over 2x the MMA work.
// A staged as [NROWS+2 rows][130 x][CINP+8 ch] fp16 (no 9x im2col dup);
// tap (ky,kx) A-fragments are ldmatrix at shifted addresses.
// B staged as [NMAX][9*CINP+8] fp16; n-groups >= NMAX skipped (conv3 padding).
// GUIDIN (conv1): A-staging computes disparity-warp + guidance inline.
template <int CIN, int CINP, int COUT, int NM, int WN, int NMAX, int NROWS,
          bool FP16OUT, bool GUIDIN>
__global__ void __launch_bounds__(256)
conv3x3_mma(const u32* __restrict__ in,    // half2 planes [b][CIN/2][H][W]
            const u32* __restrict__ wB,    // packed fp16 pairs [n][K9/2]
            const float* __restrict__ bng, const float* __restrict__ bnb,
            const float* __restrict__ bnm, const float* __restrict__ bnv,
            const float* __restrict__ coarse, const float* __restrict__ normal,
            const float* __restrict__ left,   const float* __restrict__ right,
            void* __restrict__ outp) {
    constexpr int K9   = 9 * CINP;
    constexpr int KP   = K9 + 8;       // B row stride (fp16), conflict-free
    constexpr int ASTR = CINP + 8;     // A x-stride (fp16), conflict-free
    constexpr int PP   = CINP / 2;
    constexpr int NI   = WN / 8;
    constexpr int MI   = 2 * NROWS;    // 16-px blocks per warp
    constexpr int HR   = NROWS + 2;    // halo rows
    constexpr int MWR  = 4 / NROWS;    // m-warps per output row

    extern __shared__ char smem[];
    __half* sB = (__half*)smem;                           // NMAX * KP
    __half* sA = (__half*)(smem + (size_t)NMAX * KP * 2); // HR*130*ASTR

    const int tid = threadIdx.x;
    const int x0 = blockIdx.x * 128;
    const int ybase = blockIdx.y * NROWS;
    const int b = blockIdx.z;

    // ---- stage B (u32 copy of packed fp16 pairs) ----
    for (int i = tid; i < NMAX * (K9 / 2); i += 256) {
        int n = i / (K9 / 2), j = i % (K9 / 2);
        *(u32*)(sB + (size_t)n * KP + 2 * j) = __ldg(wB + i);
    }

    if (GUIDIN) {
        // ---- stage A with inline warp + guidance (conv1, CINP=16) ----
        for (int i = tid; i < HR * 130; i += 256) {
            int r = i / 130, xloc = i % 130;
            int yy = ybase + r - 1, xx = x0 - 1 + xloc;
            u32 pk[8] = {0, 0, 0, 0, 0, 0, 0, 0};
            if (yy >= 0 && yy < Hh && (unsigned)xx < (unsigned)Ww) {
                size_t pix = (size_t)yy * Ww + xx;
                float disp = __ldg(coarse + (size_t)b * HW + pix);
                float xsf  = (float)xx - disp;
                float x0f  = floorf(xsf);
                int   xi0  = (int)x0f;
                float w1   = xsf - x0f;
                float w0   = 1.0f - w1;
                float we[3] = {0.f, 0.f, 0.f};
#pragma unroll
                for (int d = 0; d < 2; ++d) {
                    int   xi = xi0 + d;
                    float vv = (xi >= 0 && xi < Ww) ? 1.0f : 0.0f;
                    int   xc = min(max(xi, 0), Ww - 1);
                    float w  = (d == 0) ? w0 : w1;
#pragma unroll
                    for (int c = 0; c < 3; ++c)
                        we[c] += w * vv *
                            __ldg(right + ((size_t)(b * 3 + c) * Hh + yy) * Ww + xc);
                }
                float v[12];
#pragma unroll
                for (int c = 0; c < 3; ++c) {
                    v[c]     = __ldg(normal + (size_t)(b * 3 + c) * HW + pix);
                    v[3 + c] = __ldg(left   + (size_t)(b * 3 + c) * HW + pix);
                    v[6 + c] = __ldg(right  + (size_t)(b * 3 + c) * HW + pix);
                    v[9 + c] = we[c] - v[3 + c];
                }
#pragma unroll
                for (int p = 0; p < 6; ++p) {
                    __half2 h = __floats2half2_rn(v[2 * p], v[2 * p + 1]);
                    pk[p] = *(u32*)&h;
                }
            }
            u32* dst = (u32*)(sA + (size_t)(r * 130 + xloc) * ASTR);
            *(uint4*)dst       = make_uint4(pk[0], pk[1], pk[2], pk[3]);
            *(uint4*)(dst + 4) = make_uint4(pk[4], pk[5], pk[6], pk[7]);
        }
    } else {
        // ---- stage A: HR rows x 130 x CINP fp16 ----
        const u32* inb = in + (size_t)b * (CIN / 2) * HW;
        for (int i = tid; i < HR * PP * 130; i += 256) {
            int xloc = i % 130;
            int rp   = i / 130;
            int r = rp / PP, p = rp % PP;
            int yy = ybase + r - 1, xx = x0 - 1 + xloc;
            u32 v = 0;
            if (p < CIN / 2 && yy >= 0 && yy < Hh && (unsigned)xx < (unsigned)Ww)
                v = __ldg(inb + (size_t)p * HW + (size_t)yy * Ww + xx);
            *(u32*)(sA + ((size_t)(r * 130 + xloc)) * ASTR + 2 * p) = v;
        }
    }
    __syncthreads();

    const int lane = tid & 31, wid = tid >> 5;
    const int wm = wid & 3, wn = wid >> 2;
    const int yrow  = wm / MWR;             // which output row this warp owns
    const int xbase = (wm % MWR) * (MI * 16);

    const u32 aBase = smem_u32(sA);
    const u32 bBase = smem_u32(sB);
    const int rowA = lane & 15;
    const int kofA = (lane >> 4) * 8;
    const int rowB = lane & 7;
    const int kofB = ((lane >> 3) & 1) * 8;

    float d[MI][NI][4];
#pragma unroll
    for (int mi = 0; mi < MI; ++mi)
#pragma unroll
        for (int ni = 0; ni < NI; ++ni)
#pragma unroll
            for (int c = 0; c < 4; ++c) d[mi][ni][c] = 0.0f;

#pragma unroll
    for (int t = 0; t < 9; ++t) {
        const int ky = t / 3, kx = t % 3;
        const u32 aT = aBase +
            (u32)((((ky + yrow) * 130 + xbase + rowA + kx) * ASTR + kofA) * 2);
        const u32 bRow = bBase + (u32)((((wn * WN + rowB) * KP) + t * CINP + kofB) * 2);
#pragma unroll
        for (int kk = 0; kk < CINP / 16; ++kk) {
            u32 a[MI][4];
#pragma unroll
            for (int mi = 0; mi < MI; ++mi)
                ldmA(a[mi], aT + (u32)(mi * 16 * ASTR * 2) + kk * 32);
#pragma unroll
            for (int ni = 0; ni < NI; ++ni) {
                if (NMAX == NM || wn * WN + ni * 8 < NMAX) {
                    u32 bb[2];
                    ldmB(bb, bRow + (u32)(ni * 8 * KP * 2) + kk * 32);
#pragma unroll
                    for (int mi = 0; mi < MI; ++mi)
                        mma16816(d[mi][ni], a[mi], bb);
                }
            }
        }
    }

    // ---- epilogue ----
    const int r4 = lane >> 2, c4 = lane & 3;
    const int yo = ybase + yrow;
#pragma unroll
    for (int ni = 0; ni < NI; ++ni) {
        int ch = wn * WN + ni * 8 + c4 * 2;
        if (FP16OUT) {
            float s0 = __ldg(bng + ch)     * rsqrtf(__ldg(bnv + ch) + 1e-5f);
            float t0 = __ldg(bnb + ch)     - __ldg(bnm + ch) * s0;
            float s1 = __ldg(bng + ch + 1) * rsqrtf(__ldg(bnv + ch + 1) + 1e-5f);
            float t1 = __ldg(bnb + ch + 1) - __ldg(bnm + ch + 1) * s1;
#pragma unroll
            for (int mi = 0; mi < MI; ++mi) {
                int x = x0 + xbase + mi * 16 + r4;
                u32* oh = (u32*)outp + (size_t)b * (COUT / 2) * HW
                                     + (size_t)(ch >> 1) * HW + (size_t)yo * Ww;
                float v00 = fmaxf(d[mi][ni][0] * s0 + t0, 0.f);
                float v01 = fmaxf(d[mi][ni][1] * s1 + t1, 0.f);
                float v10 = fmaxf(d[mi][ni][2] * s0 + t0, 0.f);
                float v11 = fmaxf(d[mi][ni][3] * s1 + t1, 0.f);
                __half2 h0 = __floats2half2_rn(v00, v01);
                __half2 h1 = __floats2half2_rn(v10, v11);
                oh[x]     = *(u32*)&h0;
                oh[x + 8] = *(u32*)&h1;
            }
        } else if (ch < COUT) {
#pragma unroll
            for (int mi = 0; mi < MI; ++mi) {
                int x = x0 + xbase + mi * 16 + r4;
                float* of = (float*)outp + (size_t)b * COUT * HW + (size_t)yo * Ww;
                of[(size_t)ch * HW + x]           = d[mi][ni][0];
                of[(size_t)(ch + 1) * HW + x]     = d[mi][ni][1];
                of[(size_t)ch * HW + x + 8]       = d[mi][ni][2];
                of[(size_t)(ch + 1) * HW + x + 8] = d[mi][ni][3];
            }
        }
    }
}

// ---------------- kernel 5: affinity normalization + propagation -------------
__global__ void propagate_k(const float* __restrict__ oa,
                            const float* __restrict__ conf,
                            const float* __restrict__ coarse,
                            const float* __restrict__ ascp,
                            float* __restrict__ out) {
    int idx = blockIdx.x * blockDim.x + threadIdx.x;
    if (idx >= BHW) return;
    int x = idx % Ww;
    int y = (idx / Ww) % Hh;
    int b = idx / HW;

    const float asc = __ldg(ascp) + 1e-8f;
    const float* oab   = oa + (size_t)b * 24 * HW + (size_t)y * Ww + x;
    const float* confb = conf + (size_t)b * HW;
    const float* coarb = coarse + (size_t)b * HW;

    float offy[8], offx[8], aff[8];
#pragma unroll
    for (int n = 0; n < 8; ++n) {
        offy[n] = __ldg(oab + (size_t)(2 * n) * HW);
        offx[n] = __ldg(oab + (size_t)(2 * n + 1) * HW);
        float a = tanhf(__ldg(oab + (size_t)(16 + n) * HW)) / asc;
        float ca = bilin(confb, (float)y + offy[n], (float)x + offx[n]);
        aff[n] = a * ca;
    }
    float s = 1e-4f;
#pragma unroll
    for (int n = 0; n < 8; ++n) s += fabsf(aff[n]);
    s = fmaxf(s, 1.0f);
    float suma = 0.0f;
#pragma unroll
    for (int n = 0; n < 8; ++n) { aff[n] /= s; suma += aff[n]; }
    float aref = 1.0f - suma;

    float inter = 0.0f;
#pragma unroll
    for (int k = 0; k < 9; ++k) {
        float ky = (float)(k / 3) - 1.0f;
        float kx = (float)(k % 3) - 1.0f;
        float oy, ox, a;
        if (k < 4)       { oy = offy[k];     ox = offx[k];     a = aff[k];     }
        else if (k == 4) { oy = 0.0f;        ox = 0.0f;        a = aref;       }
        else             { oy = offy[k - 1]; ox = offx[k - 1]; a = aff[k - 1]; }
        float sv = bilin(coarb, (float)y + ky + oy, (float)x + kx + ox);
        inter += a * sv;
    }
    inter = fmaxf(inter, 0.0f);
    float cd = __ldg(coarb + (size_t)y * Ww + x);
    out[idx] = fmaxf(0.7f * cd + 0.3f * inter, 0.0f);
}

// ---------------- launch ------------------------------------------------------
extern "C" void kernel_launch(void* const* d_in, const int* in_sizes, int n_in,
                              void* d_out, int out_size) {
    const float* coarse  = (const float*)d_in[0];
    const float* normal  = (const float*)d_in[1];
    const float* left    = (const float*)d_in[2];
    const float* right   = (const float*)d_in[3];
    const float* conf    = (const float*)d_in[4];
    const float* conv1_w = (const float*)d_in[5];
    const float* bn1_g   = (const float*)d_in[6];
    const float* bn1_b   = (const float*)d_in[7];
    const float* bn1_m   = (const float*)d_in[8];
    const float* bn1_v   = (const float*)d_in[9];
    const float* conv2_w = (const float*)d_in[10];
    const float* bn2_g   = (const float*)d_in[11];
    const float* bn2_b   = (const float*)d_in[12];
    const float* bn2_m   = (const float*)d_in[13];
    const float* bn2_v   = (const float*)d_in[14];
    const float* conv3_w = (const float*)d_in[15];
    const float* asc     = (const float*)d_in[16];
    float* out = (float*)d_out;

    u32 *x1, *x2, *w1, *w2, *w3;
    float* oa;
    cudaGetSymbolAddress((void**)&x1, g_x1);
    cudaGetSymbolAddress((void**)&x2, g_x2);
    cudaGetSymbolAddress((void**)&oa, g_oa);
    cudaGetSymbolAddress((void**)&w1, g_w1);
    cudaGetSymbolAddress((void**)&w2, g_w2);
    cudaGetSymbolAddress((void**)&w3, g_w3);

    // smem = NMAX*(K9+8)*2 (B) + (NROWS+2)*130*(CINP+8)*2 (A)
    const int smem1 = 32 * 152 * 2 + 4 * 130 * 24 * 2;   //  34,688
    const int smem2 = 64 * 296 * 2 + 3 * 130 * 40 * 2;   //  69,088
    const int smem3 = 24 * 584 * 2 + 4 * 130 * 72 * 2;   // 102,912
    cudaFuncSetAttribute(
        (const void*)conv3x3_mma<12, 16, 32, 32, 16, 32, 2, true, true>,
        cudaFuncAttributeMaxDynamicSharedMemorySize, smem1);
    cudaFuncSetAttribute(
        (const void*)conv3x3_mma<32, 32, 64, 64, 32, 64, 1, true, false>,
        cudaFuncAttributeMaxDynamicSharedMemorySize, smem2);
    cudaFuncSetAttribute(
        (const void*)conv3x3_mma<64, 64, 24, 32, 16, 24, 2, false, false>,
        cudaFuncAttributeMaxDynamicSharedMemorySize, smem3);

    // 0) weight prep (fp32 OIHW -> packed fp16 GEMM-B)
    prep_w<<<(32 * 72 + 64 * 144 + 32 * 288 + 255) / 256, 256>>>(conv1_w, conv2_w, conv3_w);

    // 1+2) conv1 + bn + relu (12 -> 32), 2 rows/CTA, inline warp+guidance
    {
        dim3 g(Ww / 128, Hh / 2, Bn);   // (10, 192, 4)
        conv3x3_mma<12, 16, 32, 32, 16, 32, 2, true, true><<<g, 256, smem1>>>(
            nullptr, w1, bn1_g, bn1_b, bn1_m, bn1_v,
            coarse, normal, left, right, x1);
    }

    // 3) conv2 + bn + relu  (32 -> 64), 1 row/CTA (proven shape)
    {
        dim3 g(Ww / 128, Hh, Bn);       // (10, 384, 4)
        conv3x3_mma<32, 32, 64, 64, 32, 64, 1, true, false><<<g, 256, smem2>>>(
            x1, w2, bn2_g, bn2_b, bn2_m, bn2_v,
            nullptr, nullptr, nullptr, nullptr, x2);
    }

    // 4) conv3 (64 -> 24, NMAX=24), 2 rows/CTA, MI=4 for ILP
    {
        dim3 g(Ww / 128, Hh / 2, Bn);   // (10, 192, 4)
        conv3x3_mma<64, 64, 24, 32, 16, 24, 2, false, false><<<g, 256, smem3>>>(
            x2, w3, nullptr, nullptr, nullptr, nullptr,
            nullptr, nullptr, nullptr, nullptr, oa);
    }

    // 5) propagation epilogue
    propagate_k<<<(BHW + 255) / 256, 256>>>(oa, conf, coarse, asc, out);
}